// round 11
// baseline (speedup 1.0000x reference)
#include <cuda_runtime.h>
#include <cuda_bf16.h>
#include <cstdint>
#include <cstddef>

#define BB 8
#define NN 1024
#define HH 8
#define DD 64
#define CC (HH*DD)   // 512

// Scratch
__device__ __nv_bfloat16 g_hpH[BB*NN*CC];
__device__ __nv_bfloat16 g_hpL[BB*NN*CC];
__device__ __nv_bfloat16 g_oWH[CC*DD];
__device__ __nv_bfloat16 g_oWL[CC*DD];
__device__ float g_s   [BB*HH*NN];
__device__ float g_t   [BB*HH*NN];
__device__ float g_es  [BB*HH*NN];
__device__ float g_es01[BB*HH*NN];
__device__ float g_et  [BB*HH*NN];
__device__ float g_et01[BB*HH*NN];
__device__ float g_Wh[BB*NN*CC];
// sort/scan pipeline scratch
__device__ int   g_tpi [BB*HH*NN];
__device__ float g_wA  [BB*HH*NN];
__device__ float g_wB  [BB*HH*NN];
__device__ int   g_ci  [BB*HH*NN];
__device__ int   g_qord[BB*HH*NN];
__device__ int   g_bofG[BB*HH*16];
__device__ float g_prA [BB*HH*8*64];
__device__ float g_prB [BB*HH*8*64];
__device__ float g_TotA[BB*HH*64];

__device__ __forceinline__ uint32_t smem_u32(const void* p) {
    uint32_t a;
    asm("{ .reg .u64 t; cvta.to.shared.u64 t, %1; cvt.u32.u64 %0, t; }" : "=r"(a) : "l"(p));
    return a;
}
#define LDSM4(r0, r1, r2, r3, addr) \
    asm volatile("ldmatrix.sync.aligned.m8n8.x4.shared.b16 {%0,%1,%2,%3}, [%4];" \
                 : "=r"(r0), "=r"(r1), "=r"(r2), "=r"(r3) : "r"(addr))
#define LDSM_T4(r0, r1, r2, r3, addr) \
    asm volatile("ldmatrix.sync.aligned.m8n8.x4.trans.shared.b16 {%0,%1,%2,%3}, [%4];" \
                 : "=r"(r0), "=r"(r1), "=r"(r2), "=r"(r3) : "r"(addr))
#define MMA16816(d0,d1,d2,d3, a0,a1,a2,a3, b0,b1) \
    asm volatile("mma.sync.aligned.m16n8k16.row.col.f32.bf16.bf16.f32 " \
                 "{%0,%1,%2,%3}, {%4,%5,%6,%7}, {%8,%9}, {%0,%1,%2,%3};" \
                 : "+f"(d0), "+f"(d1), "+f"(d2), "+f"(d3) \
                 : "r"(a0), "r"(a1), "r"(a2), "r"(a3), "r"(b0), "r"(b1))

// ---------------------------------------------------------------------------
// kW: split out_W into bf16 hi/lo.
// ---------------------------------------------------------------------------
__global__ __launch_bounds__(256) void kW_conv(const float* __restrict__ oW) {
    int i = blockIdx.x * 256 + threadIdx.x;
    float v = oW[i];
    __nv_bfloat16 hi = __float2bfloat16_rn(v);
    g_oWH[i] = hi;
    g_oWL[i] = __float2bfloat16_rn(v - __bfloat162float(hi));
}

// ---------------------------------------------------------------------------
// k1x: Wh = h @ W (64-row x one-head tile per block) fused with s/t/exp.
// ---------------------------------------------------------------------------
__global__ __launch_bounds__(256) void k1x(const float* __restrict__ h,
                                           const float* __restrict__ W,
                                           const float* __restrict__ a) {
    __shared__ __align__(16) float As[64][68];   // [row][k]
    __shared__ __align__(16) float Bs[64][68];   // [k][col]
    __shared__ float as[128];
    __shared__ float sred[64][17], tred[64][17];
    int tid = threadIdx.x;
    int hh = blockIdx.x;
    int r0 = blockIdx.y * 64;
    int c0 = hh * 64;
    if (tid < 128) as[tid] = a[tid];
#pragma unroll
    for (int p = 0; p < 4; p++) {
        int idx = p * 256 + tid;
        int r = idx >> 4, k4 = idx & 15;
        *(float4*)&As[r][k4*4] = *(const float4*)&h[(size_t)(r0 + r) * 64 + k4*4];
        *(float4*)&Bs[r][k4*4] = *(const float4*)&W[(size_t)r * CC + c0 + k4*4];
    }
    __syncthreads();
    int tx = tid & 15, ty = tid >> 4;
    float acc[4][4] = {};
#pragma unroll
    for (int k4 = 0; k4 < 16; k4++) {
        float4 a4[4], b4[4];
#pragma unroll
        for (int r = 0; r < 4; r++) a4[r] = *(const float4*)&As[ty*4+r][k4*4];
#pragma unroll
        for (int kk = 0; kk < 4; kk++) b4[kk] = *(const float4*)&Bs[k4*4+kk][tx*4];
#pragma unroll
        for (int kk = 0; kk < 4; kk++) {
            float ak[4] = { kk==0?a4[0].x:kk==1?a4[0].y:kk==2?a4[0].z:a4[0].w,
                            kk==0?a4[1].x:kk==1?a4[1].y:kk==2?a4[1].z:a4[1].w,
                            kk==0?a4[2].x:kk==1?a4[2].y:kk==2?a4[2].z:a4[2].w,
                            kk==0?a4[3].x:kk==1?a4[3].y:kk==2?a4[3].z:a4[3].w };
            float bk[4] = { b4[kk].x, b4[kk].y, b4[kk].z, b4[kk].w };
#pragma unroll
            for (int r = 0; r < 4; r++)
#pragma unroll
                for (int c = 0; c < 4; c++)
                    acc[r][c] = fmaf(ak[r], bk[c], acc[r][c]);
        }
    }
#pragma unroll
    for (int r = 0; r < 4; r++) {
        float4 o = {acc[r][0], acc[r][1], acc[r][2], acc[r][3]};
        *(float4*)&g_Wh[(size_t)(r0 + ty*4 + r) * CC + c0 + tx*4] = o;
        float ps = 0.f, pt = 0.f;
#pragma unroll
        for (int c = 0; c < 4; c++) {
            ps = fmaf(acc[r][c], as[tx*4 + c], ps);
            pt = fmaf(acc[r][c], as[64 + tx*4 + c], pt);
        }
        sred[ty*4 + r][tx] = ps;
        tred[ty*4 + r][tx] = pt;
    }
    __syncthreads();
    if (tid < 64) {
        float s = 0.f, t = 0.f;
#pragma unroll
        for (int x = 0; x < 16; x++) { s += sred[tid][x]; t += tred[tid][x]; }
        int gr = r0 + tid;
        int b = gr >> 10, n = gr & (NN - 1);
        int o = (b * HH + hh) * NN + n;
        g_s[o] = s;                 g_t[o] = t;
        g_es[o]   = __expf(s);      g_es01[o] = __expf(0.01f * s);
        g_et[o]   = __expf(t);      g_et01[o] = __expf(0.01f * t);
    }
}

// ---------------------------------------------------------------------------
__device__ __forceinline__ int ub1024(const float* __restrict__ arr, float key) {
    int lo = 0, hi = 1024;
    while (lo < hi) {
        int mid = (lo + hi) >> 1;
        if (arr[mid] <= key) lo = mid + 1; else hi = mid;
    }
    return lo;
}

// register compare-exchange for both key/idx pairs (intra-warp, j<=16)
__device__ __forceinline__ void shfl_cex(int e, int k, int j,
                                         float& ks, int& is,
                                         float& kt2, int& it2) {
    bool up = ((e & k) == 0);
    bool amLow = ((e & j) == 0);
    float pks = __shfl_xor_sync(0xFFFFFFFFu, ks, j);
    int   pis = __shfl_xor_sync(0xFFFFFFFFu, is, j);
    float pkt = __shfl_xor_sync(0xFFFFFFFFu, kt2, j);
    int   pit = __shfl_xor_sync(0xFFFFFFFFu, it2, j);
    bool c1 = amLow ? ((ks > pks) == up) : ((pks > ks) == up);
    if (c1) { ks = pks; is = pis; }
    bool c2 = amLow ? ((kt2 > pkt) == up) : ((pkt > kt2) == up);
    if (c2) { kt2 = pkt; it2 = pit; }
}

// ---------------------------------------------------------------------------
// kS: one block per (b,h), 1024 threads. Sorts (shuffle-accelerated bitonic),
//     warp-shuffle scans, Z, buckets, chunk sums, coarse prefixes.
// ---------------------------------------------------------------------------
#define S_SV    0
#define S_TV    1024
#define S_SIDX  2048
#define S_TPI   3072
#define S_SCANA 4096    /* 1024 incl values + 32 warp sums */
#define S_SCANB 6144
#define S_WAS   8192
#define S_WBS   9216
#define S_PARTA 10240
#define S_PARTB 11264
#define S_BOFF  12288
#define S_CNT   12304
#define KS_FLOATS 12320
#define KS_SMEM (KS_FLOATS * 4)

__global__ __launch_bounds__(1024) void kS_all() {
    extern __shared__ float sm[];
    float* sv    = sm + S_SV;
    float* tv    = sm + S_TV;
    int*   sidx  = (int*)(sm + S_SIDX);
    int*   tpi   = (int*)(sm + S_TPI);
    float* scanA = sm + S_SCANA;
    float* scanB = sm + S_SCANB;
    float* wAs   = sm + S_WAS;
    float* wBs   = sm + S_WBS;
    float* partA = sm + S_PARTA;
    float* partB = sm + S_PARTB;
    int*   boff  = (int*)(sm + S_BOFF);
    int*   cnt   = (int*)(sm + S_CNT);

    int tid = threadIdx.x;
    int lane = tid & 31, wrp = tid >> 5;
    int bh = blockIdx.x;
    int b = bh >> 3, hh = bh & 7;
    int base = bh * NN;

    float s0 = g_s[base + tid];
    sv[tid] = s0;  sidx[tid] = tid;
    tv[tid] = g_t[base + tid];  tpi[tid] = tid;
    if (tid < 16) { boff[tid] = 0; cnt[tid] = 0; }
    __syncthreads();

    // ---- bitonic sort, dual arrays; all j<=16 phases in registers ----
    {
        float ksv = sv[tid]; int kis = sidx[tid];
        float ktv = tv[tid]; int kit = tpi[tid];
        // k = 2..32: every phase intra-warp
#pragma unroll
        for (int k = 2; k <= 32; k <<= 1)
#pragma unroll
            for (int j = k >> 1; j > 0; j >>= 1)
                shfl_cex(tid, k, j, ksv, kis, ktv, kit);
        sv[tid] = ksv; sidx[tid] = kis; tv[tid] = ktv; tpi[tid] = kit;
        __syncthreads();
        for (int k = 64; k <= 1024; k <<= 1) {
            for (int j = k >> 1; j >= 32; j >>= 1) {
                int ixj = tid ^ j;
                if (ixj > tid) {
                    bool up = ((tid & k) == 0);
                    float av = sv[tid], bq = sv[ixj];
                    if ((av > bq) == up) {
                        sv[tid] = bq; sv[ixj] = av;
                        int tmp = sidx[tid]; sidx[tid] = sidx[ixj]; sidx[ixj] = tmp;
                    }
                    float at = tv[tid], bt = tv[ixj];
                    if ((at > bt) == up) {
                        tv[tid] = bt; tv[ixj] = at;
                        int tmp = tpi[tid]; tpi[tid] = tpi[ixj]; tpi[ixj] = tmp;
                    }
                }
                __syncthreads();
            }
            // register tail j = 16..1
            ksv = sv[tid]; kis = sidx[tid]; ktv = tv[tid]; kit = tpi[tid];
#pragma unroll
            for (int j = 16; j > 0; j >>= 1)
                shfl_cex(tid, k, j, ksv, kis, ktv, kit);
            sv[tid] = ksv; sidx[tid] = kis; tv[tid] = ktv; tpi[tid] = kit;
            __syncthreads();
        }
    }

    // ---- inclusive scans of es/es01 in s-sorted order (warp shuffles) ----
    {
        int io = sidx[tid];
        float aA = g_es[base + io];
        float aB = g_es01[base + io];
#pragma unroll
        for (int d = 1; d < 32; d <<= 1) {
            float uA = __shfl_up_sync(0xFFFFFFFFu, aA, d);
            float uB = __shfl_up_sync(0xFFFFFFFFu, aB, d);
            if (lane >= d) { aA += uA; aB += uB; }
        }
        if (lane == 31) { scanA[1024 + wrp] = aA; scanB[1024 + wrp] = aB; }
        __syncthreads();
        if (wrp == 0) {
            float wa = scanA[1024 + lane], wb = scanB[1024 + lane];
#pragma unroll
            for (int d = 1; d < 32; d <<= 1) {
                float uA = __shfl_up_sync(0xFFFFFFFFu, wa, d);
                float uB = __shfl_up_sync(0xFFFFFFFFu, wb, d);
                if (lane >= d) { wa += uA; wb += uB; }
            }
            scanA[1024 + lane] = wa; scanB[1024 + lane] = wb;
        }
        __syncthreads();
        float offA = wrp ? scanA[1024 + wrp - 1] : 0.f;
        float offB = wrp ? scanB[1024 + wrp - 1] : 0.f;
        scanA[tid] = aA + offA;
        scanB[tid] = aB + offB;
    }
    __syncthreads();
    const float* inclA = scanA;
    const float* inclB = scanB;
    float ES_tot = inclA[1023];

    {
        int cpr = ub1024(sv, -tv[tid]);
        int jo = tpi[tid];
        float et = g_et[base + jo], et01 = g_et01[base + jo];
        float pa = cpr ? inclA[cpr - 1] : 0.f;
        float pb = cpr ? inclB[cpr - 1] : 0.f;
        float rz = 1.f / (et * (ES_tot - pa) + et01 * pb);
        float wa = et * rz, wb = et01 * rz;
        wAs[tid] = wa;  wBs[tid] = wb;
        g_wA[base + tid] = wa;
        g_wB[base + tid] = wb;
        g_tpi[base + tid] = jo;
    }

    {
        int c = ub1024(tv, -s0);
        g_ci[base + tid] = c;
        int bu = (c == 0) ? 0 : (1 + ((c - 1) >> 7));
        atomicAdd(&boff[bu + 1], 1);
    }
    __syncthreads();

    {
        int ch = tid >> 7;
        int mh = (tid >> 6) & 1;
        int d = tid & 63;
        int m0 = ch * 128 + mh * 64;
        float pa = 0.f, pb = 0.f;
#pragma unroll 4
        for (int q = 0; q < 64; q++) {
            int m = m0 + q;
            float v = g_Wh[(size_t)(b * NN + tpi[m]) * CC + hh * DD + d];
            pa = fmaf(wAs[m], v, pa);
            pb = fmaf(wBs[m], v, pb);
        }
        partA[(ch * 2 + mh) * 64 + d] = pa;
        partB[(ch * 2 + mh) * 64 + d] = pb;
    }
    __syncthreads();

    if (tid == 0)
        for (int q = 1; q <= 9; q++) boff[q] += boff[q - 1];
    __syncthreads();

    {
        int c = g_ci[base + tid];
        int bu = (c == 0) ? 0 : (1 + ((c - 1) >> 7));
        int pos = boff[bu] + atomicAdd(&cnt[bu], 1);
        g_qord[base + pos] = tid;
    }
    if (tid < 16) g_bofG[bh * 16 + tid] = boff[tid];

    if (tid < 64) {
        int d = tid;
        float pa = 0.f, pb = 0.f;
#pragma unroll
        for (int ch = 0; ch < 8; ch++) {
            int o = (bh * 8 + ch) * 64 + d;
            g_prA[o] = pa;  g_prB[o] = pb;
            pa += partA[(ch * 2) * 64 + d] + partA[(ch * 2 + 1) * 64 + d];
            pb += partB[(ch * 2) * 64 + d] + partB[(ch * 2 + 1) * 64 + d];
        }
        g_TotA[bh * 64 + d] = pa;
    }
}

// ---------------------------------------------------------------------------
// kD: stage chunk Wh rows into smem; 64 threads run BOTH prefix chains
//     (locA written in place over stage) while 192 threads gather query
//     metadata; serve queries from smem. ~70 KB smem -> 3 CTA/SM.
// grid 512 = bh*8+ch, 256 threads, dynamic smem.
// ---------------------------------------------------------------------------
#define D_STAGE  0        /* 128 x 64, becomes locA after the scan */
#define D_LOCB   8192
#define D_WA     16384
#define D_WB     16512
#define D_TOT    16640
#define D_PRA    16704
#define D_PRB    16768
#define D_TPI    16832    /* 128 ints */
#define D_QPK    16960    /* 1024 ints: i | (off+1)<<16 */
#define KD_FLOATS 17984
#define KD_SMEM (KD_FLOATS * 4)

__device__ __forceinline__ void store_hilo(size_t o, float val) {
    __nv_bfloat16 hi = __float2bfloat16_rn(val);
    g_hpH[o] = hi;
    g_hpL[o] = __float2bfloat16_rn(val - __bfloat162float(hi));
}

__global__ __launch_bounds__(256) void kD_apply() {
    extern __shared__ float sm[];
    float* stage = sm + D_STAGE;   // aliases locA after scan
    float* locB = sm + D_LOCB;
    float* wAs  = sm + D_WA;
    float* wBs  = sm + D_WB;
    float* Tot  = sm + D_TOT;
    float* prA  = sm + D_PRA;
    float* prB  = sm + D_PRB;
    int*   tpis = (int*)(sm + D_TPI);
    int*   qpk  = (int*)(sm + D_QPK);

    int tid = threadIdx.x;
    int bh = blockIdx.x >> 3, ch = blockIdx.x & 7;
    int b = bh >> 3, hh = bh & 7;
    int base = bh * NN;
    int cbase = base + ch * 128;

    int qs = (ch == 0) ? g_bofG[bh * 16 + 0] : g_bofG[bh * 16 + ch + 1];
    int qe = g_bofG[bh * 16 + ch + 2];
    int nq = qe - qs;

    if (tid < 128) {
        wAs[tid] = g_wA[cbase + tid];
        wBs[tid] = g_wB[cbase + tid];
        tpis[tid] = g_tpi[cbase + tid];
    } else if (tid < 192) {
        int d = tid - 128;
        Tot[d] = g_TotA[bh * 64 + d];
        prA[d] = g_prA[(bh * 8 + ch) * 64 + d];
        prB[d] = g_prB[(bh * 8 + ch) * 64 + d];
    }
    __syncthreads();

    // stage: 128 rows x 64 floats, coalesced float4 gather (all threads)
#pragma unroll
    for (int p = 0; p < 8; p++) {
        int idx = p * 256 + tid;
        int m = idx >> 4, f4 = idx & 15;
        *(float4*)&stage[m * 64 + f4 * 4] =
            *(const float4*)&g_Wh[(size_t)(b * NN + tpis[m]) * CC + hh * DD + f4 * 4];
    }
    __syncthreads();

    if (tid < 64) {
        // both prefix chains in one pass; locA overwrites stage in place
        int d = tid;
        float runA = 0.f, runB = 0.f;
#pragma unroll 8
        for (int m = 0; m < 128; m++) {
            float v = stage[m * 64 + d];
            runA = fmaf(wAs[m], v, runA);
            runB = fmaf(wBs[m], v, runB);
            stage[m * 64 + d] = runA;
            locB[m * 64 + d] = runB;
        }
    } else {
        // parallel query-metadata gather
        int t2 = tid - 64;
        for (int q = qs + t2; q < qe; q += 192) {
            int i = g_qord[base + q];
            int c = g_ci[base + i];
            int off = c - ch * 128 - 1;     // -1 only for bucket-0 (ch==0)
            qpk[q - qs] = i | ((off + 1) << 16);
        }
    }
    __syncthreads();

    // serve queries (locA == stage)
    {
        int qg = tid >> 6, d = tid & 63;
        for (int q = qg; q < nq; q += 4) {
            int pk = qpk[q];
            int i = pk & 0xFFFF;
            int offp = pk >> 16;
            float es = g_es[base + i];
            float val;
            if (offp == 0) {
                val = es * Tot[d];
            } else {
                int off = offp - 1;
                float es01 = g_es01[base + i];
                val = es * (Tot[d] - prA[d] - stage[off * 64 + d])
                    + es01 * (prB[d] + locB[off * 64 + d]);
            }
            store_hilo((size_t)(b * NN + i) * CC + hh * DD + d, val);
        }
    }
}

// ---------------------------------------------------------------------------
// k5m: out = h' @ out_W + b via mma.sync bf16 hi/lo (3 MMAs, fp32 acc).
// ---------------------------------------------------------------------------
__global__ __launch_bounds__(256) void k5m(const float* __restrict__ ob,
                                           float* __restrict__ out) {
    __shared__ __align__(16) __nv_bfloat16 Ah[32][72];
    __shared__ __align__(16) __nv_bfloat16 Al[32][72];
    __shared__ __align__(16) __nv_bfloat16 Bh[64][72];
    __shared__ __align__(16) __nv_bfloat16 Bl[64][72];
    int tid = threadIdx.x, lane = tid & 31, w = tid >> 5;
    int mi = w & 1, nc = w >> 1;
    int r0 = blockIdx.x * 32;

    uint32_t aoff = (uint32_t)(((((lane >> 3) & 1) * 8 + (lane & 7)) + mi * 16) * 72
                               + (lane >> 4) * 8) * 2;
    uint32_t boff = (uint32_t)((lane & 15) * 72 + (lane >> 4) * 8) * 2
                    + (uint32_t)nc * 32;
    uint32_t aAh = smem_u32(Ah) + aoff;
    uint32_t aAl = smem_u32(Al) + aoff;
    uint32_t aBh = smem_u32(Bh) + boff;
    uint32_t aBl = smem_u32(Bl) + boff;

    float acc[2][4] = {};

    for (int kt = 0; kt < CC; kt += 64) {
        __syncthreads();
        {
            int row = tid >> 3, g = tid & 7;
            *(uint4*)&Ah[row][g*8] =
                *(const uint4*)&g_hpH[(size_t)(r0 + row) * CC + kt + g*8];
            *(uint4*)&Al[row][g*8] =
                *(const uint4*)&g_hpL[(size_t)(r0 + row) * CC + kt + g*8];
        }
#pragma unroll
        for (int p = 0; p < 2; p++) {
            int idx = p * 256 + tid;
            int row = idx >> 3, g = idx & 7;
            *(uint4*)&Bh[row][g*8] = *(const uint4*)&g_oWH[(size_t)(kt + row) * 64 + g*8];
            *(uint4*)&Bl[row][g*8] = *(const uint4*)&g_oWL[(size_t)(kt + row) * 64 + g*8];
        }
        __syncthreads();

#pragma unroll
        for (int kk = 0; kk < 4; kk++) {
            uint32_t ka = (uint32_t)(kk * 32);
            uint32_t kb = (uint32_t)(kk * 16 * 144);
            uint32_t ah0, ah1, ah2, ah3, al0, al1, al2, al3;
            uint32_t bh0, bh1, bh2, bh3, bl0, bl1, bl2, bl3;
            LDSM4(ah0, ah1, ah2, ah3, aAh + ka);
            LDSM4(al0, al1, al2, al3, aAl + ka);
            LDSM_T4(bh0, bh1, bh2, bh3, aBh + kb);
            LDSM_T4(bl0, bl1, bl2, bl3, aBl + kb);
            MMA16816(acc[0][0], acc[0][1], acc[0][2], acc[0][3],
                     ah0, ah1, ah2, ah3, bh0, bh1);
            MMA16816(acc[1][0], acc[1][1], acc[1][2], acc[1][3],
                     ah0, ah1, ah2, ah3, bh2, bh3);
            MMA16816(acc[0][0], acc[0][1], acc[0][2], acc[0][3],
                     ah0, ah1, ah2, ah3, bl0, bl1);
            MMA16816(acc[1][0], acc[1][1], acc[1][2], acc[1][3],
                     ah0, ah1, ah2, ah3, bl2, bl3);
            MMA16816(acc[0][0], acc[0][1], acc[0][2], acc[0][3],
                     al0, al1, al2, al3, bh0, bh1);
            MMA16816(acc[1][0], acc[1][1], acc[1][2], acc[1][3],
                     al0, al1, al2, al3, bh2, bh3);
        }
    }

    int gr = lane >> 2, c2 = (lane & 3) * 2;
    int row0 = r0 + mi * 16 + gr;
#pragma unroll
    for (int t = 0; t < 2; t++) {
        int col = nc * 16 + t * 8 + c2;
        float b0 = ob[col], b1 = ob[col + 1];
        float2 o0 = {acc[t][0] + b0, acc[t][1] + b1};
        float2 o1 = {acc[t][2] + b0, acc[t][3] + b1};
        *(float2*)&out[(size_t)row0 * DD + col] = o0;
        *(float2*)&out[(size_t)(row0 + 8) * DD + col] = o1;
    }
}

// ---------------------------------------------------------------------------
extern "C" void kernel_launch(void* const* d_in, const int* in_sizes, int n_in,
                              void* d_out, int out_size) {
    const float* h    = (const float*)d_in[0];
    const float* W    = (const float*)d_in[2];
    const float* a    = (const float*)d_in[3];
    const float* oW   = (const float*)d_in[4];
    const float* ob   = (const float*)d_in[5];
    float* out = (float*)d_out;

    cudaFuncSetAttribute(kS_all, cudaFuncAttributeMaxDynamicSharedMemorySize,
                         KS_SMEM);
    cudaFuncSetAttribute(kD_apply, cudaFuncAttributeMaxDynamicSharedMemorySize,
                         KD_SMEM);

    kW_conv<<<(CC*DD)/256, 256>>>(oW);
    k1x<<<dim3(HH, (BB*NN)/64), 256>>>(h, W, a);
    kS_all<<<BB*HH, 1024, KS_SMEM>>>();
    kD_apply<<<BB*HH*8, 256, KD_SMEM>>>();
    k5m<<<(BB*NN)/32, 256>>>(ob, out);
}

// round 12
// speedup vs baseline: 1.1178x; 1.1178x over previous
#include <cuda_runtime.h>
#include <cuda_bf16.h>
#include <cstdint>
#include <cstddef>

#define BB 8
#define NN 1024
#define HH 8
#define DD 64
#define CC (HH*DD)   // 512

// Scratch
__device__ __nv_bfloat16 g_hpH[BB*NN*CC];
__device__ __nv_bfloat16 g_hpL[BB*NN*CC];
__device__ __nv_bfloat16 g_oWH[CC*DD];
__device__ __nv_bfloat16 g_oWL[CC*DD];
__device__ float g_s   [BB*HH*NN];
__device__ float g_t   [BB*HH*NN];
__device__ float g_es  [BB*HH*NN];
__device__ float g_es01[BB*HH*NN];
__device__ float g_et  [BB*HH*NN];
__device__ float g_et01[BB*HH*NN];
__device__ float g_Wh[BB*NN*CC];
// sort/scan pipeline scratch
__device__ int   g_tpi [BB*HH*NN];
__device__ float g_wA  [BB*HH*NN];
__device__ float g_wB  [BB*HH*NN];
__device__ int   g_ci  [BB*HH*NN];
__device__ int   g_qord[BB*HH*NN];
__device__ int   g_bofG[BB*HH*16];
__device__ float g_prA [BB*HH*8*64];
__device__ float g_prB [BB*HH*8*64];
__device__ float g_TotA[BB*HH*64];

__device__ __forceinline__ uint32_t smem_u32(const void* p) {
    uint32_t a;
    asm("{ .reg .u64 t; cvta.to.shared.u64 t, %1; cvt.u32.u64 %0, t; }" : "=r"(a) : "l"(p));
    return a;
}
#define LDSM4(r0, r1, r2, r3, addr) \
    asm volatile("ldmatrix.sync.aligned.m8n8.x4.shared.b16 {%0,%1,%2,%3}, [%4];" \
                 : "=r"(r0), "=r"(r1), "=r"(r2), "=r"(r3) : "r"(addr))
#define LDSM_T4(r0, r1, r2, r3, addr) \
    asm volatile("ldmatrix.sync.aligned.m8n8.x4.trans.shared.b16 {%0,%1,%2,%3}, [%4];" \
                 : "=r"(r0), "=r"(r1), "=r"(r2), "=r"(r3) : "r"(addr))
#define MMA16816(d0,d1,d2,d3, a0,a1,a2,a3, b0,b1) \
    asm volatile("mma.sync.aligned.m16n8k16.row.col.f32.bf16.bf16.f32 " \
                 "{%0,%1,%2,%3}, {%4,%5,%6,%7}, {%8,%9}, {%0,%1,%2,%3};" \
                 : "+f"(d0), "+f"(d1), "+f"(d2), "+f"(d3) \
                 : "r"(a0), "r"(a1), "r"(a2), "r"(a3), "r"(b0), "r"(b1))

// ---------------------------------------------------------------------------
// k1x: Wh = h @ W (64-row x one-head tile per block) fused with s/t/exp.
// ---------------------------------------------------------------------------
__global__ __launch_bounds__(256) void k1x(const float* __restrict__ h,
                                           const float* __restrict__ W,
                                           const float* __restrict__ a) {
    __shared__ __align__(16) float As[64][68];   // [row][k]
    __shared__ __align__(16) float Bs[64][68];   // [k][col]
    __shared__ float as[128];
    __shared__ float sred[64][17], tred[64][17];
    int tid = threadIdx.x;
    int hh = blockIdx.x;
    int r0 = blockIdx.y * 64;
    int c0 = hh * 64;
    if (tid < 128) as[tid] = a[tid];
#pragma unroll
    for (int p = 0; p < 4; p++) {
        int idx = p * 256 + tid;
        int r = idx >> 4, k4 = idx & 15;
        *(float4*)&As[r][k4*4] = *(const float4*)&h[(size_t)(r0 + r) * 64 + k4*4];
        *(float4*)&Bs[r][k4*4] = *(const float4*)&W[(size_t)r * CC + c0 + k4*4];
    }
    __syncthreads();
    int tx = tid & 15, ty = tid >> 4;
    float acc[4][4] = {};
#pragma unroll
    for (int k4 = 0; k4 < 16; k4++) {
        float4 a4[4], b4[4];
#pragma unroll
        for (int r = 0; r < 4; r++) a4[r] = *(const float4*)&As[ty*4+r][k4*4];
#pragma unroll
        for (int kk = 0; kk < 4; kk++) b4[kk] = *(const float4*)&Bs[k4*4+kk][tx*4];
#pragma unroll
        for (int kk = 0; kk < 4; kk++) {
            float ak[4] = { kk==0?a4[0].x:kk==1?a4[0].y:kk==2?a4[0].z:a4[0].w,
                            kk==0?a4[1].x:kk==1?a4[1].y:kk==2?a4[1].z:a4[1].w,
                            kk==0?a4[2].x:kk==1?a4[2].y:kk==2?a4[2].z:a4[2].w,
                            kk==0?a4[3].x:kk==1?a4[3].y:kk==2?a4[3].z:a4[3].w };
            float bk[4] = { b4[kk].x, b4[kk].y, b4[kk].z, b4[kk].w };
#pragma unroll
            for (int r = 0; r < 4; r++)
#pragma unroll
                for (int c = 0; c < 4; c++)
                    acc[r][c] = fmaf(ak[r], bk[c], acc[r][c]);
        }
    }
#pragma unroll
    for (int r = 0; r < 4; r++) {
        float4 o = {acc[r][0], acc[r][1], acc[r][2], acc[r][3]};
        *(float4*)&g_Wh[(size_t)(r0 + ty*4 + r) * CC + c0 + tx*4] = o;
        float ps = 0.f, pt = 0.f;
#pragma unroll
        for (int c = 0; c < 4; c++) {
            ps = fmaf(acc[r][c], as[tx*4 + c], ps);
            pt = fmaf(acc[r][c], as[64 + tx*4 + c], pt);
        }
        sred[ty*4 + r][tx] = ps;
        tred[ty*4 + r][tx] = pt;
    }
    __syncthreads();
    if (tid < 64) {
        float s = 0.f, t = 0.f;
#pragma unroll
        for (int x = 0; x < 16; x++) { s += sred[tid][x]; t += tred[tid][x]; }
        int gr = r0 + tid;
        int b = gr >> 10, n = gr & (NN - 1);
        int o = (b * HH + hh) * NN + n;
        g_s[o] = s;                 g_t[o] = t;
        g_es[o]   = __expf(s);      g_es01[o] = __expf(0.01f * s);
        g_et[o]   = __expf(t);      g_et01[o] = __expf(0.01f * t);
    }
}

// ---------------------------------------------------------------------------
__device__ __forceinline__ int ub1024(const float* __restrict__ arr, float key) {
    int lo = 0, hi = 1024;
    while (lo < hi) {
        int mid = (lo + hi) >> 1;
        if (arr[mid] <= key) lo = mid + 1; else hi = mid;
    }
    return lo;
}

// register compare-exchange for both key/idx pairs (intra-warp, j<=16)
__device__ __forceinline__ void shfl_cex(int e, int k, int j,
                                         float& ks, int& is,
                                         float& kt2, int& it2) {
    bool up = ((e & k) == 0);
    bool amLow = ((e & j) == 0);
    float pks = __shfl_xor_sync(0xFFFFFFFFu, ks, j);
    int   pis = __shfl_xor_sync(0xFFFFFFFFu, is, j);
    float pkt = __shfl_xor_sync(0xFFFFFFFFu, kt2, j);
    int   pit = __shfl_xor_sync(0xFFFFFFFFu, it2, j);
    bool c1 = amLow ? ((ks > pks) == up) : ((pks > ks) == up);
    if (c1) { ks = pks; is = pis; }
    bool c2 = amLow ? ((kt2 > pkt) == up) : ((pkt > kt2) == up);
    if (c2) { kt2 = pkt; it2 = pit; }
}

// ---------------------------------------------------------------------------
// kS: one block per (b,h), 1024 threads. Also converts out_W to bf16 hi/lo
//     (independent work, folded here to save a launch). Shuffle-accelerated
//     bitonic sorts, warp-shuffle scans, Z, buckets, chunk sums, prefixes.
// ---------------------------------------------------------------------------
#define S_SV    0
#define S_TV    1024
#define S_SIDX  2048
#define S_TPI   3072
#define S_SCANA 4096    /* 1024 incl values + 32 warp sums */
#define S_SCANB 6144
#define S_WAS   8192
#define S_WBS   9216
#define S_PARTA 10240
#define S_PARTB 11264
#define S_BOFF  12288
#define S_CNT   12304
#define KS_FLOATS 12320
#define KS_SMEM (KS_FLOATS * 4)

__global__ __launch_bounds__(1024) void kS_all(const float* __restrict__ oW) {
    extern __shared__ float sm[];
    float* sv    = sm + S_SV;
    float* tv    = sm + S_TV;
    int*   sidx  = (int*)(sm + S_SIDX);
    int*   tpi   = (int*)(sm + S_TPI);
    float* scanA = sm + S_SCANA;
    float* scanB = sm + S_SCANB;
    float* wAs   = sm + S_WAS;
    float* wBs   = sm + S_WBS;
    float* partA = sm + S_PARTA;
    float* partB = sm + S_PARTB;
    int*   boff  = (int*)(sm + S_BOFF);
    int*   cnt   = (int*)(sm + S_CNT);

    int tid = threadIdx.x;
    int lane = tid & 31, wrp = tid >> 5;
    int bh = blockIdx.x;
    int b = bh >> 3, hh = bh & 7;
    int base = bh * NN;

    // folded kW: out_W hi/lo split (blocks 0..31 cover all 32768 elements)
    {
        int i = bh * 1024 + tid;
        if (i < CC * DD) {
            float v = oW[i];
            __nv_bfloat16 hi = __float2bfloat16_rn(v);
            g_oWH[i] = hi;
            g_oWL[i] = __float2bfloat16_rn(v - __bfloat162float(hi));
        }
    }

    float s0 = g_s[base + tid];
    sv[tid] = s0;  sidx[tid] = tid;
    tv[tid] = g_t[base + tid];  tpi[tid] = tid;
    if (tid < 16) { boff[tid] = 0; cnt[tid] = 0; }
    __syncthreads();

    // ---- bitonic sort, dual arrays; all j<=16 phases in registers ----
    {
        float ksv = sv[tid]; int kis = sidx[tid];
        float ktv = tv[tid]; int kit = tpi[tid];
#pragma unroll
        for (int k = 2; k <= 32; k <<= 1)
#pragma unroll
            for (int j = k >> 1; j > 0; j >>= 1)
                shfl_cex(tid, k, j, ksv, kis, ktv, kit);
        sv[tid] = ksv; sidx[tid] = kis; tv[tid] = ktv; tpi[tid] = kit;
        __syncthreads();
        for (int k = 64; k <= 1024; k <<= 1) {
            for (int j = k >> 1; j >= 32; j >>= 1) {
                int ixj = tid ^ j;
                if (ixj > tid) {
                    bool up = ((tid & k) == 0);
                    float av = sv[tid], bq = sv[ixj];
                    if ((av > bq) == up) {
                        sv[tid] = bq; sv[ixj] = av;
                        int tmp = sidx[tid]; sidx[tid] = sidx[ixj]; sidx[ixj] = tmp;
                    }
                    float at = tv[tid], bt = tv[ixj];
                    if ((at > bt) == up) {
                        tv[tid] = bt; tv[ixj] = at;
                        int tmp = tpi[tid]; tpi[tid] = tpi[ixj]; tpi[ixj] = tmp;
                    }
                }
                __syncthreads();
            }
            ksv = sv[tid]; kis = sidx[tid]; ktv = tv[tid]; kit = tpi[tid];
#pragma unroll
            for (int j = 16; j > 0; j >>= 1)
                shfl_cex(tid, k, j, ksv, kis, ktv, kit);
            sv[tid] = ksv; sidx[tid] = kis; tv[tid] = ktv; tpi[tid] = kit;
            __syncthreads();
        }
    }

    // ---- inclusive scans of es/es01 in s-sorted order (warp shuffles) ----
    {
        int io = sidx[tid];
        float aA = g_es[base + io];
        float aB = g_es01[base + io];
#pragma unroll
        for (int d = 1; d < 32; d <<= 1) {
            float uA = __shfl_up_sync(0xFFFFFFFFu, aA, d);
            float uB = __shfl_up_sync(0xFFFFFFFFu, aB, d);
            if (lane >= d) { aA += uA; aB += uB; }
        }
        if (lane == 31) { scanA[1024 + wrp] = aA; scanB[1024 + wrp] = aB; }
        __syncthreads();
        if (wrp == 0) {
            float wa = scanA[1024 + lane], wb = scanB[1024 + lane];
#pragma unroll
            for (int d = 1; d < 32; d <<= 1) {
                float uA = __shfl_up_sync(0xFFFFFFFFu, wa, d);
                float uB = __shfl_up_sync(0xFFFFFFFFu, wb, d);
                if (lane >= d) { wa += uA; wb += uB; }
            }
            scanA[1024 + lane] = wa; scanB[1024 + lane] = wb;
        }
        __syncthreads();
        float offA = wrp ? scanA[1024 + wrp - 1] : 0.f;
        float offB = wrp ? scanB[1024 + wrp - 1] : 0.f;
        scanA[tid] = aA + offA;
        scanB[tid] = aB + offB;
    }
    __syncthreads();
    const float* inclA = scanA;
    const float* inclB = scanB;
    float ES_tot = inclA[1023];

    {
        int cpr = ub1024(sv, -tv[tid]);
        int jo = tpi[tid];
        float et = g_et[base + jo], et01 = g_et01[base + jo];
        float pa = cpr ? inclA[cpr - 1] : 0.f;
        float pb = cpr ? inclB[cpr - 1] : 0.f;
        float rz = 1.f / (et * (ES_tot - pa) + et01 * pb);
        float wa = et * rz, wb = et01 * rz;
        wAs[tid] = wa;  wBs[tid] = wb;
        g_wA[base + tid] = wa;
        g_wB[base + tid] = wb;
        g_tpi[base + tid] = jo;
    }

    {
        int c = ub1024(tv, -s0);
        g_ci[base + tid] = c;
        int bu = (c == 0) ? 0 : (1 + ((c - 1) >> 7));
        atomicAdd(&boff[bu + 1], 1);
    }
    __syncthreads();

    {
        int ch = tid >> 7;
        int mh = (tid >> 6) & 1;
        int d = tid & 63;
        int m0 = ch * 128 + mh * 64;
        float pa = 0.f, pb = 0.f;
#pragma unroll 4
        for (int q = 0; q < 64; q++) {
            int m = m0 + q;
            float v = g_Wh[(size_t)(b * NN + tpi[m]) * CC + hh * DD + d];
            pa = fmaf(wAs[m], v, pa);
            pb = fmaf(wBs[m], v, pb);
        }
        partA[(ch * 2 + mh) * 64 + d] = pa;
        partB[(ch * 2 + mh) * 64 + d] = pb;
    }
    __syncthreads();

    if (tid == 0)
        for (int q = 1; q <= 9; q++) boff[q] += boff[q - 1];
    __syncthreads();

    {
        int c = g_ci[base + tid];
        int bu = (c == 0) ? 0 : (1 + ((c - 1) >> 7));
        int pos = boff[bu] + atomicAdd(&cnt[bu], 1);
        g_qord[base + pos] = tid;
    }
    if (tid < 16) g_bofG[bh * 16 + tid] = boff[tid];

    if (tid < 64) {
        int d = tid;
        float pa = 0.f, pb = 0.f;
#pragma unroll
        for (int ch = 0; ch < 8; ch++) {
            int o = (bh * 8 + ch) * 64 + d;
            g_prA[o] = pa;  g_prB[o] = pb;
            pa += partA[(ch * 2) * 64 + d] + partA[(ch * 2 + 1) * 64 + d];
            pb += partB[(ch * 2) * 64 + d] + partB[(ch * 2 + 1) * 64 + d];
        }
        g_TotA[bh * 64 + d] = pa;
    }
}

// ---------------------------------------------------------------------------
// kD (R10 structure): stage chunk Wh rows into smem, 128-thread dual scan
//     while threads 128-255 gather query metadata (incl. es/es01) into smem;
//     serve queries from smem with Tot/prA/prB hoisted to registers.
// grid 512 = bh*8+ch, 256 threads, dynamic smem (~112 KB, 2 CTA/SM).
// ---------------------------------------------------------------------------
#define D_STAGE  0        /* 128 x 64 */
#define D_LOCA   8192
#define D_LOCB   16384
#define D_WA     24576
#define D_WB     24704
#define D_TOT    24832
#define D_PRA    24896
#define D_PRB    24960
#define D_TPI    25024    /* 128 ints */
#define D_QPK    25152    /* 1024 ints: i | (off+1)<<16 */
#define D_QES    26176    /* 1024 floats */
#define D_QES01  27200    /* 1024 floats */
#define KD_FLOATS 28224
#define KD_SMEM (KD_FLOATS * 4)

__device__ __forceinline__ void store_hilo(size_t o, float val) {
    __nv_bfloat16 hi = __float2bfloat16_rn(val);
    g_hpH[o] = hi;
    g_hpL[o] = __float2bfloat16_rn(val - __bfloat162float(hi));
}

__global__ __launch_bounds__(256) void kD_apply() {
    extern __shared__ float sm[];
    float* stage = sm + D_STAGE;
    float* locA = sm + D_LOCA;
    float* locB = sm + D_LOCB;
    float* wAs  = sm + D_WA;
    float* wBs  = sm + D_WB;
    float* Tot  = sm + D_TOT;
    float* prA  = sm + D_PRA;
    float* prB  = sm + D_PRB;
    int*   tpis = (int*)(sm + D_TPI);
    int*   qpk  = (int*)(sm + D_QPK);
    float* qes  = sm + D_QES;
    float* qes01= sm + D_QES01;

    int tid = threadIdx.x;
    int bh = blockIdx.x >> 3, ch = blockIdx.x & 7;
    int b = bh >> 3, hh = bh & 7;
    int base = bh * NN;
    int cbase = base + ch * 128;

    int qs = (ch == 0) ? g_bofG[bh * 16 + 0] : g_bofG[bh * 16 + ch + 1];
    int qe = g_bofG[bh * 16 + ch + 2];
    int nq = qe - qs;

    if (tid < 128) {
        wAs[tid] = g_wA[cbase + tid];
        wBs[tid] = g_wB[cbase + tid];
        tpis[tid] = g_tpi[cbase + tid];
    } else if (tid < 192) {
        int d = tid - 128;
        Tot[d] = g_TotA[bh * 64 + d];
        prA[d] = g_prA[(bh * 8 + ch) * 64 + d];
        prB[d] = g_prB[(bh * 8 + ch) * 64 + d];
    }
    __syncthreads();

    // stage: 128 rows x 64 floats, coalesced float4 gather (all threads)
#pragma unroll
    for (int p = 0; p < 8; p++) {
        int idx = p * 256 + tid;
        int m = idx >> 4, f4 = idx & 15;
        *(float4*)&stage[m * 64 + f4 * 4] =
            *(const float4*)&g_Wh[(size_t)(b * NN + tpis[m]) * CC + hh * DD + f4 * 4];
    }
    __syncthreads();

    if (tid < 128) {
        // local prefix scans (serial chain only over FMA latency)
        int half = tid >> 6, d = tid & 63;
        const float* w = half ? wBs : wAs;
        float* loc = half ? locB : locA;
        float run = 0.f;
#pragma unroll 8
        for (int m = 0; m < 128; m++) {
            run = fmaf(w[m], stage[m * 64 + d], run);
            loc[m * 64 + d] = run;
        }
    } else {
        // parallel query-metadata gather (high MLP, no serial chain)
        int t2 = tid - 128;
        for (int q = qs + t2; q < qe; q += 128) {
            int i = g_qord[base + q];
            int c = g_ci[base + i];
            int off = c - ch * 128 - 1;        // -1 only for bucket-0 (ch==0)
            qpk[q - qs] = i | ((off + 1) << 16);
            qes[q - qs]   = g_es[base + i];
            qes01[q - qs] = g_es01[base + i];
        }
    }
    __syncthreads();

    // serve queries from smem only; Tot/prA/prB hoisted to registers
    {
        int qg = tid >> 6, d = tid & 63;
        float totd = Tot[d], prad = prA[d], prbd = prB[d];
        float tma = totd - prad;               // Tot - prA (loop-invariant)
        for (int q = qg; q < nq; q += 4) {
            int pk = qpk[q];
            int i = pk & 0xFFFF;
            int offp = pk >> 16;               // 0 => bucket-0, else off+1
            float es = qes[q];
            float val;
            if (offp == 0) {
                val = es * totd;
            } else {
                int off = offp - 1;
                val = es * (tma - locA[off * 64 + d])
                    + qes01[q] * (prbd + locB[off * 64 + d]);
            }
            store_hilo((size_t)(b * NN + i) * CC + hh * DD + d, val);
        }
    }
}

// ---------------------------------------------------------------------------
// k5m: out = h' @ out_W + b via mma.sync bf16 hi/lo (3 MMAs, fp32 acc).
// ---------------------------------------------------------------------------
__global__ __launch_bounds__(256) void k5m(const float* __restrict__ ob,
                                           float* __restrict__ out) {
    __shared__ __align__(16) __nv_bfloat16 Ah[32][72];
    __shared__ __align__(16) __nv_bfloat16 Al[32][72];
    __shared__ __align__(16) __nv_bfloat16 Bh[64][72];
    __shared__ __align__(16) __nv_bfloat16 Bl[64][72];
    int tid = threadIdx.x, lane = tid & 31, w = tid >> 5;
    int mi = w & 1, nc = w >> 1;
    int r0 = blockIdx.x * 32;

    uint32_t aoff = (uint32_t)(((((lane >> 3) & 1) * 8 + (lane & 7)) + mi * 16) * 72
                               + (lane >> 4) * 8) * 2;
    uint32_t boff = (uint32_t)((lane & 15) * 72 + (lane >> 4) * 8) * 2
                    + (uint32_t)nc * 32;
    uint32_t aAh = smem_u32(Ah) + aoff;
    uint32_t aAl = smem_u32(Al) + aoff;
    uint32_t aBh = smem_u32(Bh) + boff;
    uint32_t aBl = smem_u32(Bl) + boff;

    float acc[2][4] = {};

    for (int kt = 0; kt < CC; kt += 64) {
        __syncthreads();
        {
            int row = tid >> 3, g = tid & 7;
            *(uint4*)&Ah[row][g*8] =
                *(const uint4*)&g_hpH[(size_t)(r0 + row) * CC + kt + g*8];
            *(uint4*)&Al[row][g*8] =
                *(const uint4*)&g_hpL[(size_t)(r0 + row) * CC + kt + g*8];
        }
#pragma unroll
        for (int p = 0; p < 2; p++) {
            int idx = p * 256 + tid;
            int row = idx >> 3, g = idx & 7;
            *(uint4*)&Bh[row][g*8] = *(const uint4*)&g_oWH[(size_t)(kt + row) * 64 + g*8];
            *(uint4*)&Bl[row][g*8] = *(const uint4*)&g_oWL[(size_t)(kt + row) * 64 + g*8];
        }
        __syncthreads();

#pragma unroll
        for (int kk = 0; kk < 4; kk++) {
            uint32_t ka = (uint32_t)(kk * 32);
            uint32_t kb = (uint32_t)(kk * 16 * 144);
            uint32_t ah0, ah1, ah2, ah3, al0, al1, al2, al3;
            uint32_t bh0, bh1, bh2, bh3, bl0, bl1, bl2, bl3;
            LDSM4(ah0, ah1, ah2, ah3, aAh + ka);
            LDSM4(al0, al1, al2, al3, aAl + ka);
            LDSM_T4(bh0, bh1, bh2, bh3, aBh + kb);
            LDSM_T4(bl0, bl1, bl2, bl3, aBl + kb);
            MMA16816(acc[0][0], acc[0][1], acc[0][2], acc[0][3],
                     ah0, ah1, ah2, ah3, bh0, bh1);
            MMA16816(acc[1][0], acc[1][1], acc[1][2], acc[1][3],
                     ah0, ah1, ah2, ah3, bh2, bh3);
            MMA16816(acc[0][0], acc[0][1], acc[0][2], acc[0][3],
                     ah0, ah1, ah2, ah3, bl0, bl1);
            MMA16816(acc[1][0], acc[1][1], acc[1][2], acc[1][3],
                     ah0, ah1, ah2, ah3, bl2, bl3);
            MMA16816(acc[0][0], acc[0][1], acc[0][2], acc[0][3],
                     al0, al1, al2, al3, bh0, bh1);
            MMA16816(acc[1][0], acc[1][1], acc[1][2], acc[1][3],
                     al0, al1, al2, al3, bh2, bh3);
        }
    }

    int gr = lane >> 2, c2 = (lane & 3) * 2;
    int row0 = r0 + mi * 16 + gr;
#pragma unroll
    for (int t = 0; t < 2; t++) {
        int col = nc * 16 + t * 8 + c2;
        float b0 = ob[col], b1 = ob[col + 1];
        float2 o0 = {acc[t][0] + b0, acc[t][1] + b1};
        float2 o1 = {acc[t][2] + b0, acc[t][3] + b1};
        *(float2*)&out[(size_t)row0 * DD + col] = o0;
        *(float2*)&out[(size_t)(row0 + 8) * DD + col] = o1;
    }
}

// ---------------------------------------------------------------------------
extern "C" void kernel_launch(void* const* d_in, const int* in_sizes, int n_in,
                              void* d_out, int out_size) {
    const float* h    = (const float*)d_in[0];
    const float* W    = (const float*)d_in[2];
    const float* a    = (const float*)d_in[3];
    const float* oW   = (const float*)d_in[4];
    const float* ob   = (const float*)d_in[5];
    float* out = (float*)d_out;

    cudaFuncSetAttribute(kS_all, cudaFuncAttributeMaxDynamicSharedMemorySize,
                         KS_SMEM);
    cudaFuncSetAttribute(kD_apply, cudaFuncAttributeMaxDynamicSharedMemorySize,
                         KD_SMEM);

    k1x<<<dim3(HH, (BB*NN)/64), 256>>>(h, W, a);
    kS_all<<<BB*HH, 1024, KS_SMEM>>>(oW);
    kD_apply<<<BB*HH*8, 256, KD_SMEM>>>();
    k5m<<<(BB*NN)/32, 256>>>(ob, out);
}

// round 13
// speedup vs baseline: 1.2167x; 1.0884x over previous
#include <cuda_runtime.h>
#include <cuda_bf16.h>
#include <cstdint>
#include <cstddef>

#define BB 8
#define NN 1024
#define HH 8
#define DD 64
#define CC (HH*DD)   // 512

// Scratch
__device__ __nv_bfloat16 g_hpH[BB*NN*CC];
__device__ __nv_bfloat16 g_hpL[BB*NN*CC];
__device__ __nv_bfloat16 g_oWH[CC*DD];
__device__ __nv_bfloat16 g_oWL[CC*DD];
__device__ float g_s   [BB*HH*NN];
__device__ float g_t   [BB*HH*NN];
__device__ float g_es  [BB*HH*NN];
__device__ float g_es01[BB*HH*NN];
__device__ float g_et  [BB*HH*NN];
__device__ float g_et01[BB*HH*NN];
__device__ float g_Wh[BB*NN*CC];
// sort/scan pipeline scratch (16 chunks of 64)
__device__ int   g_tpi [BB*HH*NN];
__device__ float g_wA  [BB*HH*NN];
__device__ float g_wB  [BB*HH*NN];
__device__ int   g_ci  [BB*HH*NN];
__device__ int   g_qord[BB*HH*NN];
__device__ int   g_bofG[BB*HH*32];
__device__ float g_prA [BB*HH*16*64];
__device__ float g_prB [BB*HH*16*64];
__device__ float g_TotA[BB*HH*64];

__device__ __forceinline__ uint32_t smem_u32(const void* p) {
    uint32_t a;
    asm("{ .reg .u64 t; cvta.to.shared.u64 t, %1; cvt.u32.u64 %0, t; }" : "=r"(a) : "l"(p));
    return a;
}
#define LDSM4(r0, r1, r2, r3, addr) \
    asm volatile("ldmatrix.sync.aligned.m8n8.x4.shared.b16 {%0,%1,%2,%3}, [%4];" \
                 : "=r"(r0), "=r"(r1), "=r"(r2), "=r"(r3) : "r"(addr))
#define LDSM_T4(r0, r1, r2, r3, addr) \
    asm volatile("ldmatrix.sync.aligned.m8n8.x4.trans.shared.b16 {%0,%1,%2,%3}, [%4];" \
                 : "=r"(r0), "=r"(r1), "=r"(r2), "=r"(r3) : "r"(addr))
#define MMA16816(d0,d1,d2,d3, a0,a1,a2,a3, b0,b1) \
    asm volatile("mma.sync.aligned.m16n8k16.row.col.f32.bf16.bf16.f32 " \
                 "{%0,%1,%2,%3}, {%4,%5,%6,%7}, {%8,%9}, {%0,%1,%2,%3};" \
                 : "+f"(d0), "+f"(d1), "+f"(d2), "+f"(d3) \
                 : "r"(a0), "r"(a1), "r"(a2), "r"(a3), "r"(b0), "r"(b1))

// ---------------------------------------------------------------------------
// k1x: Wh = h @ W (64-row x one-head tile per block) fused with s/t/exp.
// ---------------------------------------------------------------------------
__global__ __launch_bounds__(256) void k1x(const float* __restrict__ h,
                                           const float* __restrict__ W,
                                           const float* __restrict__ a) {
    __shared__ __align__(16) float As[64][68];   // [row][k]
    __shared__ __align__(16) float Bs[64][68];   // [k][col]
    __shared__ float as[128];
    __shared__ float sred[64][17], tred[64][17];
    int tid = threadIdx.x;
    int hh = blockIdx.x;
    int r0 = blockIdx.y * 64;
    int c0 = hh * 64;
    if (tid < 128) as[tid] = a[tid];
#pragma unroll
    for (int p = 0; p < 4; p++) {
        int idx = p * 256 + tid;
        int r = idx >> 4, k4 = idx & 15;
        *(float4*)&As[r][k4*4] = *(const float4*)&h[(size_t)(r0 + r) * 64 + k4*4];
        *(float4*)&Bs[r][k4*4] = *(const float4*)&W[(size_t)r * CC + c0 + k4*4];
    }
    __syncthreads();
    int tx = tid & 15, ty = tid >> 4;
    float acc[4][4] = {};
#pragma unroll
    for (int k4 = 0; k4 < 16; k4++) {
        float4 a4[4], b4[4];
#pragma unroll
        for (int r = 0; r < 4; r++) a4[r] = *(const float4*)&As[ty*4+r][k4*4];
#pragma unroll
        for (int kk = 0; kk < 4; kk++) b4[kk] = *(const float4*)&Bs[k4*4+kk][tx*4];
#pragma unroll
        for (int kk = 0; kk < 4; kk++) {
            float ak[4] = { kk==0?a4[0].x:kk==1?a4[0].y:kk==2?a4[0].z:a4[0].w,
                            kk==0?a4[1].x:kk==1?a4[1].y:kk==2?a4[1].z:a4[1].w,
                            kk==0?a4[2].x:kk==1?a4[2].y:kk==2?a4[2].z:a4[2].w,
                            kk==0?a4[3].x:kk==1?a4[3].y:kk==2?a4[3].z:a4[3].w };
            float bk[4] = { b4[kk].x, b4[kk].y, b4[kk].z, b4[kk].w };
#pragma unroll
            for (int r = 0; r < 4; r++)
#pragma unroll
                for (int c = 0; c < 4; c++)
                    acc[r][c] = fmaf(ak[r], bk[c], acc[r][c]);
        }
    }
#pragma unroll
    for (int r = 0; r < 4; r++) {
        float4 o = {acc[r][0], acc[r][1], acc[r][2], acc[r][3]};
        *(float4*)&g_Wh[(size_t)(r0 + ty*4 + r) * CC + c0 + tx*4] = o;
        float ps = 0.f, pt = 0.f;
#pragma unroll
        for (int c = 0; c < 4; c++) {
            ps = fmaf(acc[r][c], as[tx*4 + c], ps);
            pt = fmaf(acc[r][c], as[64 + tx*4 + c], pt);
        }
        sred[ty*4 + r][tx] = ps;
        tred[ty*4 + r][tx] = pt;
    }
    __syncthreads();
    if (tid < 64) {
        float s = 0.f, t = 0.f;
#pragma unroll
        for (int x = 0; x < 16; x++) { s += sred[tid][x]; t += tred[tid][x]; }
        int gr = r0 + tid;
        int b = gr >> 10, n = gr & (NN - 1);
        int o = (b * HH + hh) * NN + n;
        g_s[o] = s;                 g_t[o] = t;
        g_es[o]   = __expf(s);      g_es01[o] = __expf(0.01f * s);
        g_et[o]   = __expf(t);      g_et01[o] = __expf(0.01f * t);
    }
}

// ---------------------------------------------------------------------------
__device__ __forceinline__ int ub1024(const float* __restrict__ arr, float key) {
    int lo = 0, hi = 1024;
    while (lo < hi) {
        int mid = (lo + hi) >> 1;
        if (arr[mid] <= key) lo = mid + 1; else hi = mid;
    }
    return lo;
}

__device__ __forceinline__ void shfl_cex(int e, int k, int j,
                                         float& ks, int& is,
                                         float& kt2, int& it2) {
    bool up = ((e & k) == 0);
    bool amLow = ((e & j) == 0);
    float pks = __shfl_xor_sync(0xFFFFFFFFu, ks, j);
    int   pis = __shfl_xor_sync(0xFFFFFFFFu, is, j);
    float pkt = __shfl_xor_sync(0xFFFFFFFFu, kt2, j);
    int   pit = __shfl_xor_sync(0xFFFFFFFFu, it2, j);
    bool c1 = amLow ? ((ks > pks) == up) : ((pks > ks) == up);
    if (c1) { ks = pks; is = pis; }
    bool c2 = amLow ? ((kt2 > pkt) == up) : ((pkt > kt2) == up);
    if (c2) { kt2 = pkt; it2 = pit; }
}

// ---------------------------------------------------------------------------
// kS: one block per (b,h), 1024 threads. Folds out_W hi/lo split. Shuffle
//     bitonic sorts, warp scans, Z, 17 buckets (c==0 plus 16 chunks of 64),
//     16 chunk sums (one thread per (ch,d)), coarse prefixes.
// ---------------------------------------------------------------------------
#define S_SV    0
#define S_TV    1024
#define S_SIDX  2048
#define S_TPI   3072
#define S_SCANA 4096
#define S_SCANB 6144
#define S_WAS   8192
#define S_WBS   9216
#define S_PARTA 10240
#define S_PARTB 11264
#define S_BOFF  12288   /* 32 ints */
#define S_CNT   12320   /* 32 ints */
#define KS_FLOATS 12352
#define KS_SMEM (KS_FLOATS * 4)

__global__ __launch_bounds__(1024) void kS_all(const float* __restrict__ oW) {
    extern __shared__ float sm[];
    float* sv    = sm + S_SV;
    float* tv    = sm + S_TV;
    int*   sidx  = (int*)(sm + S_SIDX);
    int*   tpi   = (int*)(sm + S_TPI);
    float* scanA = sm + S_SCANA;
    float* scanB = sm + S_SCANB;
    float* wAs   = sm + S_WAS;
    float* wBs   = sm + S_WBS;
    float* partA = sm + S_PARTA;
    float* partB = sm + S_PARTB;
    int*   boff  = (int*)(sm + S_BOFF);
    int*   cnt   = (int*)(sm + S_CNT);

    int tid = threadIdx.x;
    int lane = tid & 31, wrp = tid >> 5;
    int bh = blockIdx.x;
    int b = bh >> 3, hh = bh & 7;
    int base = bh * NN;

    // folded kW: out_W hi/lo split (blocks 0..31 cover all 32768 elements)
    {
        int i = bh * 1024 + tid;
        if (i < CC * DD) {
            float v = oW[i];
            __nv_bfloat16 hi = __float2bfloat16_rn(v);
            g_oWH[i] = hi;
            g_oWL[i] = __float2bfloat16_rn(v - __bfloat162float(hi));
        }
    }

    float s0 = g_s[base + tid];
    sv[tid] = s0;  sidx[tid] = tid;
    tv[tid] = g_t[base + tid];  tpi[tid] = tid;
    if (tid < 32) { boff[tid] = 0; cnt[tid] = 0; }
    __syncthreads();

    // ---- bitonic sort, dual arrays; all j<=16 phases in registers ----
    {
        float ksv = sv[tid]; int kis = sidx[tid];
        float ktv = tv[tid]; int kit = tpi[tid];
#pragma unroll
        for (int k = 2; k <= 32; k <<= 1)
#pragma unroll
            for (int j = k >> 1; j > 0; j >>= 1)
                shfl_cex(tid, k, j, ksv, kis, ktv, kit);
        sv[tid] = ksv; sidx[tid] = kis; tv[tid] = ktv; tpi[tid] = kit;
        __syncthreads();
        for (int k = 64; k <= 1024; k <<= 1) {
            for (int j = k >> 1; j >= 32; j >>= 1) {
                int ixj = tid ^ j;
                if (ixj > tid) {
                    bool up = ((tid & k) == 0);
                    float av = sv[tid], bq = sv[ixj];
                    if ((av > bq) == up) {
                        sv[tid] = bq; sv[ixj] = av;
                        int tmp = sidx[tid]; sidx[tid] = sidx[ixj]; sidx[ixj] = tmp;
                    }
                    float at = tv[tid], bt = tv[ixj];
                    if ((at > bt) == up) {
                        tv[tid] = bt; tv[ixj] = at;
                        int tmp = tpi[tid]; tpi[tid] = tpi[ixj]; tpi[ixj] = tmp;
                    }
                }
                __syncthreads();
            }
            ksv = sv[tid]; kis = sidx[tid]; ktv = tv[tid]; kit = tpi[tid];
#pragma unroll
            for (int j = 16; j > 0; j >>= 1)
                shfl_cex(tid, k, j, ksv, kis, ktv, kit);
            sv[tid] = ksv; sidx[tid] = kis; tv[tid] = ktv; tpi[tid] = kit;
            __syncthreads();
        }
    }

    // ---- inclusive scans of es/es01 in s-sorted order (warp shuffles) ----
    {
        int io = sidx[tid];
        float aA = g_es[base + io];
        float aB = g_es01[base + io];
#pragma unroll
        for (int d = 1; d < 32; d <<= 1) {
            float uA = __shfl_up_sync(0xFFFFFFFFu, aA, d);
            float uB = __shfl_up_sync(0xFFFFFFFFu, aB, d);
            if (lane >= d) { aA += uA; aB += uB; }
        }
        if (lane == 31) { scanA[1024 + wrp] = aA; scanB[1024 + wrp] = aB; }
        __syncthreads();
        if (wrp == 0) {
            float wa = scanA[1024 + lane], wb = scanB[1024 + lane];
#pragma unroll
            for (int d = 1; d < 32; d <<= 1) {
                float uA = __shfl_up_sync(0xFFFFFFFFu, wa, d);
                float uB = __shfl_up_sync(0xFFFFFFFFu, wb, d);
                if (lane >= d) { wa += uA; wb += uB; }
            }
            scanA[1024 + lane] = wa; scanB[1024 + lane] = wb;
        }
        __syncthreads();
        float offA = wrp ? scanA[1024 + wrp - 1] : 0.f;
        float offB = wrp ? scanB[1024 + wrp - 1] : 0.f;
        scanA[tid] = aA + offA;
        scanB[tid] = aB + offB;
    }
    __syncthreads();
    const float* inclA = scanA;
    const float* inclB = scanB;
    float ES_tot = inclA[1023];

    {
        int cpr = ub1024(sv, -tv[tid]);
        int jo = tpi[tid];
        float et = g_et[base + jo], et01 = g_et01[base + jo];
        float pa = cpr ? inclA[cpr - 1] : 0.f;
        float pb = cpr ? inclB[cpr - 1] : 0.f;
        float rz = 1.f / (et * (ES_tot - pa) + et01 * pb);
        float wa = et * rz, wb = et01 * rz;
        wAs[tid] = wa;  wBs[tid] = wb;
        g_wA[base + tid] = wa;
        g_wB[base + tid] = wb;
        g_tpi[base + tid] = jo;
    }

    {
        int c = ub1024(tv, -s0);
        g_ci[base + tid] = c;
        int bu = (c == 0) ? 0 : (1 + ((c - 1) >> 6));   // 17 buckets
        atomicAdd(&boff[bu + 1], 1);
    }
    __syncthreads();

    // chunk sums: one thread per (ch, d), 16 x 64 = 1024
    {
        int ch = tid >> 6;
        int d = tid & 63;
        int m0 = ch * 64;
        float pa = 0.f, pb = 0.f;
#pragma unroll 4
        for (int q = 0; q < 64; q++) {
            int m = m0 + q;
            float v = g_Wh[(size_t)(b * NN + tpi[m]) * CC + hh * DD + d];
            pa = fmaf(wAs[m], v, pa);
            pb = fmaf(wBs[m], v, pb);
        }
        partA[ch * 64 + d] = pa;
        partB[ch * 64 + d] = pb;
    }
    __syncthreads();

    if (tid == 0)
        for (int q = 1; q <= 17; q++) boff[q] += boff[q - 1];
    __syncthreads();

    {
        int c = g_ci[base + tid];
        int bu = (c == 0) ? 0 : (1 + ((c - 1) >> 6));
        int pos = boff[bu] + atomicAdd(&cnt[bu], 1);
        g_qord[base + pos] = tid;
    }
    if (tid < 32) g_bofG[bh * 32 + tid] = boff[tid];

    if (tid < 64) {
        int d = tid;
        float pa = 0.f, pb = 0.f;
#pragma unroll
        for (int ch = 0; ch < 16; ch++) {
            int o = (bh * 16 + ch) * 64 + d;
            g_prA[o] = pa;  g_prB[o] = pb;
            pa += partA[ch * 64 + d];
            pb += partB[ch * 64 + d];
        }
        g_TotA[bh * 64 + d] = pa;
    }
}

// ---------------------------------------------------------------------------
// kD: 64-wide chunks. grid 1024 = bh*16+ch, 256 threads, ~63 KB smem
//     -> 3 CTA/SM. Stage, 128-thread dual scan + 128-thread metadata gather,
//     serve from smem.
// ---------------------------------------------------------------------------
#define D_STAGE  0        /* 64 x 64 */
#define D_LOCA   4096
#define D_LOCB   8192
#define D_WA     12288
#define D_WB     12352
#define D_TOT    12416
#define D_PRA    12480
#define D_PRB    12544
#define D_TPI    12608    /* 64 ints */
#define D_QPK    12672    /* 1024 ints */
#define D_QES    13696
#define D_QES01  14720
#define KD_FLOATS 15744
#define KD_SMEM (KD_FLOATS * 4)

__device__ __forceinline__ void store_hilo(size_t o, float val) {
    __nv_bfloat16 hi = __float2bfloat16_rn(val);
    g_hpH[o] = hi;
    g_hpL[o] = __float2bfloat16_rn(val - __bfloat162float(hi));
}

__global__ __launch_bounds__(256) void kD_apply() {
    extern __shared__ float sm[];
    float* stage = sm + D_STAGE;
    float* locA = sm + D_LOCA;
    float* locB = sm + D_LOCB;
    float* wAs  = sm + D_WA;
    float* wBs  = sm + D_WB;
    float* Tot  = sm + D_TOT;
    float* prA  = sm + D_PRA;
    float* prB  = sm + D_PRB;
    int*   tpis = (int*)(sm + D_TPI);
    int*   qpk  = (int*)(sm + D_QPK);
    float* qes  = sm + D_QES;
    float* qes01= sm + D_QES01;

    int tid = threadIdx.x;
    int bh = blockIdx.x >> 4, ch = blockIdx.x & 15;
    int b = bh >> 3, hh = bh & 7;
    int base = bh * NN;
    int cbase = base + ch * 64;

    int qs = (ch == 0) ? g_bofG[bh * 32 + 0] : g_bofG[bh * 32 + ch + 1];
    int qe = g_bofG[bh * 32 + ch + 2];
    int nq = qe - qs;

    if (tid < 64) {
        wAs[tid] = g_wA[cbase + tid];
        wBs[tid] = g_wB[cbase + tid];
        tpis[tid] = g_tpi[cbase + tid];
    } else if (tid < 128) {
        Tot[tid - 64] = g_TotA[bh * 64 + (tid - 64)];
    } else if (tid < 192) {
        prA[tid - 128] = g_prA[(bh * 16 + ch) * 64 + (tid - 128)];
    } else {
        prB[tid - 192] = g_prB[(bh * 16 + ch) * 64 + (tid - 192)];
    }
    __syncthreads();

    // stage: 64 rows x 64 floats
#pragma unroll
    for (int p = 0; p < 4; p++) {
        int idx = p * 256 + tid;
        int m = idx >> 4, f4 = idx & 15;
        *(float4*)&stage[m * 64 + f4 * 4] =
            *(const float4*)&g_Wh[(size_t)(b * NN + tpis[m]) * CC + hh * DD + f4 * 4];
    }
    __syncthreads();

    if (tid < 128) {
        int half = tid >> 6, d = tid & 63;
        const float* w = half ? wBs : wAs;
        float* loc = half ? locB : locA;
        float run = 0.f;
#pragma unroll 8
        for (int m = 0; m < 64; m++) {
            run = fmaf(w[m], stage[m * 64 + d], run);
            loc[m * 64 + d] = run;
        }
    } else {
        int t2 = tid - 128;
        for (int q = qs + t2; q < qe; q += 128) {
            int i = g_qord[base + q];
            int c = g_ci[base + i];
            int off = c - ch * 64 - 1;
            qpk[q - qs] = i | ((off + 1) << 16);
            qes[q - qs]   = g_es[base + i];
            qes01[q - qs] = g_es01[base + i];
        }
    }
    __syncthreads();

    {
        int qg = tid >> 6, d = tid & 63;
        float totd = Tot[d], prad = prA[d], prbd = prB[d];
        float tma = totd - prad;
        for (int q = qg; q < nq; q += 4) {
            int pk = qpk[q];
            int i = pk & 0xFFFF;
            int offp = pk >> 16;
            float es = qes[q];
            float val;
            if (offp == 0) {
                val = es * totd;
            } else {
                int off = offp - 1;
                val = es * (tma - locA[off * 64 + d])
                    + qes01[q] * (prbd + locB[off * 64 + d]);
            }
            store_hilo((size_t)(b * NN + i) * CC + hh * DD + d, val);
        }
    }
}

// ---------------------------------------------------------------------------
// k5m: out = h' @ out_W + b via mma.sync bf16 hi/lo.
// B-hi resident in smem; A hi/lo + B-lo chunks software-pipelined through
// double buffers (one sync per chunk). ~110.6 KB smem -> 2 CTA/SM, grid 256.
// ---------------------------------------------------------------------------
// bf16-element offsets in dynamic smem
#define K5_BH    0          /* 512 x 72 resident */
#define K5_AB    36864      /* 2 bufs x (Ah 32x72 + Al 32x72) */
#define K5_BLB   46080      /* 2 bufs x (64 x 72) */
#define K5_ELEMS 55296
#define K5_SMEM  (K5_ELEMS * 2)

__global__ __launch_bounds__(256) void k5m(const float* __restrict__ ob,
                                           float* __restrict__ out) {
    extern __shared__ __nv_bfloat16 smb[];
    __nv_bfloat16* Bh  = smb + K5_BH;
    __nv_bfloat16* Ab  = smb + K5_AB;    // [buf][hi:0/lo:2304][32*72]
    __nv_bfloat16* Blb = smb + K5_BLB;   // [buf][64*72]

    int tid = threadIdx.x, lane = tid & 31, w = tid >> 5;
    int mi = w & 1, nc = w >> 1;
    int r0 = blockIdx.x * 32;

    int arow = tid >> 3, ag = tid & 7;   // A fill: 32 rows x 8 groups

    // prologue: resident B-hi (512 x 64 -> stride 72), A chunk0, B-lo chunk0
#pragma unroll
    for (int p = 0; p < 16; p++) {
        int idx = p * 256 + tid;         // 0..4095
        int row = idx >> 3, g = idx & 7;
        *(uint4*)&Bh[row * 72 + g * 8] = *(const uint4*)&g_oWH[(size_t)row * 64 + g * 8];
    }
    *(uint4*)&Ab[arow * 72 + ag * 8] =
        *(const uint4*)&g_hpH[(size_t)(r0 + arow) * CC + ag * 8];
    *(uint4*)&Ab[2304 + arow * 72 + ag * 8] =
        *(const uint4*)&g_hpL[(size_t)(r0 + arow) * CC + ag * 8];
#pragma unroll
    for (int p = 0; p < 2; p++) {
        int idx = p * 256 + tid;         // 0..511
        int row = idx >> 3, g = idx & 7;
        *(uint4*)&Blb[row * 72 + g * 8] = *(const uint4*)&g_oWL[(size_t)row * 64 + g * 8];
    }
    __syncthreads();

    // lane bases
    uint32_t aoff = (uint32_t)(((((lane >> 3) & 1) * 8 + (lane & 7)) + mi * 16) * 72
                               + (lane >> 4) * 8) * 2;
    uint32_t bB = (uint32_t)((lane & 15) * 72 + (lane >> 4) * 8) * 2
                  + (uint32_t)nc * 32;
    uint32_t sAb = smem_u32(Ab);
    uint32_t sBh = smem_u32(Bh) + bB;
    uint32_t sBlb = smem_u32(Blb) + bB;

    float acc[2][4] = {};
    uint4 pH, pL, pB0, pB1;

    for (int c = 0; c < 8; c++) {
        int buf = c & 1;
        if (c < 7) {   // prefetch next chunk into registers
            pH = *(const uint4*)&g_hpH[(size_t)(r0 + arow) * CC + (c + 1) * 64 + ag * 8];
            pL = *(const uint4*)&g_hpL[(size_t)(r0 + arow) * CC + (c + 1) * 64 + ag * 8];
            int i0 = tid, i1 = 256 + tid;
            pB0 = *(const uint4*)&g_oWL[(size_t)((c + 1) * 64 + (i0 >> 3)) * 64 + (i0 & 7) * 8];
            pB1 = *(const uint4*)&g_oWL[(size_t)((c + 1) * 64 + (i1 >> 3)) * 64 + (i1 & 7) * 8];
        }

        uint32_t aAh = sAb + (uint32_t)buf * 9216 + aoff;
        uint32_t aAl = aAh + 4608;
        uint32_t aBl = sBlb + (uint32_t)buf * 9216;
#pragma unroll
        for (int kk = 0; kk < 4; kk++) {
            uint32_t ka = (uint32_t)(kk * 32);
            uint32_t rbh = (uint32_t)((c * 64 + kk * 16) * 144);
            uint32_t rbl = (uint32_t)(kk * 16 * 144);
            uint32_t ah0, ah1, ah2, ah3, al0, al1, al2, al3;
            uint32_t bh0, bh1, bh2, bh3, bl0, bl1, bl2, bl3;
            LDSM4(ah0, ah1, ah2, ah3, aAh + ka);
            LDSM4(al0, al1, al2, al3, aAl + ka);
            LDSM_T4(bh0, bh1, bh2, bh3, sBh + rbh);
            LDSM_T4(bl0, bl1, bl2, bl3, aBl + rbl);
            MMA16816(acc[0][0], acc[0][1], acc[0][2], acc[0][3],
                     ah0, ah1, ah2, ah3, bh0, bh1);
            MMA16816(acc[1][0], acc[1][1], acc[1][2], acc[1][3],
                     ah0, ah1, ah2, ah3, bh2, bh3);
            MMA16816(acc[0][0], acc[0][1], acc[0][2], acc[0][3],
                     ah0, ah1, ah2, ah3, bl0, bl1);
            MMA16816(acc[1][0], acc[1][1], acc[1][2], acc[1][3],
                     ah0, ah1, ah2, ah3, bl2, bl3);
            MMA16816(acc[0][0], acc[0][1], acc[0][2], acc[0][3],
                     al0, al1, al2, al3, bh0, bh1);
            MMA16816(acc[1][0], acc[1][1], acc[1][2], acc[1][3],
                     al0, al1, al2, al3, bh2, bh3);
        }

        if (c < 7) {   // store prefetched data into the other buffer
            int nb = buf ^ 1;
            *(uint4*)&Ab[nb * 4608 + arow * 72 + ag * 8] = pH;
            *(uint4*)&Ab[nb * 4608 + 2304 + arow * 72 + ag * 8] = pL;
            int i0 = tid, i1 = 256 + tid;
            *(uint4*)&Blb[nb * 4608 + (i0 >> 3) * 72 + (i0 & 7) * 8] = pB0;
            *(uint4*)&Blb[nb * 4608 + (i1 >> 3) * 72 + (i1 & 7) * 8] = pB1;
        }
        __syncthreads();
    }

    int gr = lane >> 2, c2 = (lane & 3) * 2;
    int row0 = r0 + mi * 16 + gr;
#pragma unroll
    for (int t = 0; t < 2; t++) {
        int col = nc * 16 + t * 8 + c2;
        float b0 = ob[col], b1 = ob[col + 1];
        float2 o0 = {acc[t][0] + b0, acc[t][1] + b1};
        float2 o1 = {acc[t][2] + b0, acc[t][3] + b1};
        *(float2*)&out[(size_t)row0 * DD + col] = o0;
        *(float2*)&out[(size_t)(row0 + 8) * DD + col] = o1;
    }
}

// ---------------------------------------------------------------------------
extern "C" void kernel_launch(void* const* d_in, const int* in_sizes, int n_in,
                              void* d_out, int out_size) {
    const float* h    = (const float*)d_in[0];
    const float* W    = (const float*)d_in[2];
    const float* a    = (const float*)d_in[3];
    const float* oW   = (const float*)d_in[4];
    const float* ob   = (const float*)d_in[5];
    float* out = (float*)d_out;

    cudaFuncSetAttribute(kS_all, cudaFuncAttributeMaxDynamicSharedMemorySize,
                         KS_SMEM);
    cudaFuncSetAttribute(kD_apply, cudaFuncAttributeMaxDynamicSharedMemorySize,
                         KD_SMEM);
    cudaFuncSetAttribute(k5m, cudaFuncAttributeMaxDynamicSharedMemorySize,
                         K5_SMEM);

    k1x<<<dim3(HH, (BB*NN)/64), 256>>>(h, W, a);
    kS_all<<<BB*HH, 1024, KS_SMEM>>>(oW);
    kD_apply<<<BB*HH*16, 256, KD_SMEM>>>();
    k5m<<<(BB*NN)/32, 256, K5_SMEM>>>(ob, out);
}

// round 14
// speedup vs baseline: 1.2178x; 1.0009x over previous
#include <cuda_runtime.h>
#include <cuda_bf16.h>
#include <cstdint>
#include <cstddef>

#define BB 8
#define NN 1024
#define HH 8
#define DD 64
#define CC (HH*DD)   // 512

// Scratch
__device__ __nv_bfloat16 g_hpH[BB*NN*CC];
__device__ __nv_bfloat16 g_hpL[BB*NN*CC];
__device__ __nv_bfloat16 g_oWH[CC*DD];
__device__ __nv_bfloat16 g_oWL[CC*DD];
__device__ float g_s   [BB*HH*NN];
__device__ float g_t   [BB*HH*NN];
__device__ float g_es  [BB*HH*NN];
__device__ float g_es01[BB*HH*NN];
__device__ float g_et  [BB*HH*NN];
__device__ float g_et01[BB*HH*NN];
__device__ float g_Wh[BB*NN*CC];
// sort/scan pipeline scratch (16 chunks of 64)
__device__ int   g_tpi [BB*HH*NN];
__device__ float g_wA  [BB*HH*NN];
__device__ float g_wB  [BB*HH*NN];
__device__ int   g_ci  [BB*HH*NN];
__device__ int   g_qord[BB*HH*NN];
__device__ int   g_bofG[BB*HH*32];
__device__ float g_prA [BB*HH*16*64];
__device__ float g_prB [BB*HH*16*64];
__device__ float g_TotA[BB*HH*64];

__device__ __forceinline__ uint32_t smem_u32(const void* p) {
    uint32_t a;
    asm("{ .reg .u64 t; cvta.to.shared.u64 t, %1; cvt.u32.u64 %0, t; }" : "=r"(a) : "l"(p));
    return a;
}
#define LDSM4(r0, r1, r2, r3, addr) \
    asm volatile("ldmatrix.sync.aligned.m8n8.x4.shared.b16 {%0,%1,%2,%3}, [%4];" \
                 : "=r"(r0), "=r"(r1), "=r"(r2), "=r"(r3) : "r"(addr))
#define LDSM_T4(r0, r1, r2, r3, addr) \
    asm volatile("ldmatrix.sync.aligned.m8n8.x4.trans.shared.b16 {%0,%1,%2,%3}, [%4];" \
                 : "=r"(r0), "=r"(r1), "=r"(r2), "=r"(r3) : "r"(addr))
#define MMA16816(d0,d1,d2,d3, a0,a1,a2,a3, b0,b1) \
    asm volatile("mma.sync.aligned.m16n8k16.row.col.f32.bf16.bf16.f32 " \
                 "{%0,%1,%2,%3}, {%4,%5,%6,%7}, {%8,%9}, {%0,%1,%2,%3};" \
                 : "+f"(d0), "+f"(d1), "+f"(d2), "+f"(d3) \
                 : "r"(a0), "r"(a1), "r"(a2), "r"(a3), "r"(b0), "r"(b1))
#define CP16(dst, src) \
    asm volatile("cp.async.cg.shared.global [%0], [%1], 16;" :: "r"(dst), "l"(src))
#define CP_COMMIT() asm volatile("cp.async.commit_group;" ::: "memory")
#define CP_WAIT2()  asm volatile("cp.async.wait_group 2;" ::: "memory")

// ---------------------------------------------------------------------------
// k1x: Wh = h @ W (64-row x one-head tile per block) fused with s/t/exp.
// ---------------------------------------------------------------------------
__global__ __launch_bounds__(256) void k1x(const float* __restrict__ h,
                                           const float* __restrict__ W,
                                           const float* __restrict__ a) {
    __shared__ __align__(16) float As[64][68];   // [row][k]
    __shared__ __align__(16) float Bs[64][68];   // [k][col]
    __shared__ float as[128];
    __shared__ float sred[64][17], tred[64][17];
    int tid = threadIdx.x;
    int hh = blockIdx.x;
    int r0 = blockIdx.y * 64;
    int c0 = hh * 64;
    if (tid < 128) as[tid] = a[tid];
#pragma unroll
    for (int p = 0; p < 4; p++) {
        int idx = p * 256 + tid;
        int r = idx >> 4, k4 = idx & 15;
        *(float4*)&As[r][k4*4] = *(const float4*)&h[(size_t)(r0 + r) * 64 + k4*4];
        *(float4*)&Bs[r][k4*4] = *(const float4*)&W[(size_t)r * CC + c0 + k4*4];
    }
    __syncthreads();
    int tx = tid & 15, ty = tid >> 4;
    float acc[4][4] = {};
#pragma unroll
    for (int k4 = 0; k4 < 16; k4++) {
        float4 a4[4], b4[4];
#pragma unroll
        for (int r = 0; r < 4; r++) a4[r] = *(const float4*)&As[ty*4+r][k4*4];
#pragma unroll
        for (int kk = 0; kk < 4; kk++) b4[kk] = *(const float4*)&Bs[k4*4+kk][tx*4];
#pragma unroll
        for (int kk = 0; kk < 4; kk++) {
            float ak[4] = { kk==0?a4[0].x:kk==1?a4[0].y:kk==2?a4[0].z:a4[0].w,
                            kk==0?a4[1].x:kk==1?a4[1].y:kk==2?a4[1].z:a4[1].w,
                            kk==0?a4[2].x:kk==1?a4[2].y:kk==2?a4[2].z:a4[2].w,
                            kk==0?a4[3].x:kk==1?a4[3].y:kk==2?a4[3].z:a4[3].w };
            float bk[4] = { b4[kk].x, b4[kk].y, b4[kk].z, b4[kk].w };
#pragma unroll
            for (int r = 0; r < 4; r++)
#pragma unroll
                for (int c = 0; c < 4; c++)
                    acc[r][c] = fmaf(ak[r], bk[c], acc[r][c]);
        }
    }
#pragma unroll
    for (int r = 0; r < 4; r++) {
        float4 o = {acc[r][0], acc[r][1], acc[r][2], acc[r][3]};
        *(float4*)&g_Wh[(size_t)(r0 + ty*4 + r) * CC + c0 + tx*4] = o;
        float ps = 0.f, pt = 0.f;
#pragma unroll
        for (int c = 0; c < 4; c++) {
            ps = fmaf(acc[r][c], as[tx*4 + c], ps);
            pt = fmaf(acc[r][c], as[64 + tx*4 + c], pt);
        }
        sred[ty*4 + r][tx] = ps;
        tred[ty*4 + r][tx] = pt;
    }
    __syncthreads();
    if (tid < 64) {
        float s = 0.f, t = 0.f;
#pragma unroll
        for (int x = 0; x < 16; x++) { s += sred[tid][x]; t += tred[tid][x]; }
        int gr = r0 + tid;
        int b = gr >> 10, n = gr & (NN - 1);
        int o = (b * HH + hh) * NN + n;
        g_s[o] = s;                 g_t[o] = t;
        g_es[o]   = __expf(s);      g_es01[o] = __expf(0.01f * s);
        g_et[o]   = __expf(t);      g_et01[o] = __expf(0.01f * t);
    }
}

// ---------------------------------------------------------------------------
__device__ __forceinline__ int ub1024(const float* __restrict__ arr, float key) {
    int lo = 0, hi = 1024;
    while (lo < hi) {
        int mid = (lo + hi) >> 1;
        if (arr[mid] <= key) lo = mid + 1; else hi = mid;
    }
    return lo;
}

__device__ __forceinline__ void shfl_cex(int e, int k, int j,
                                         float& ks, int& is,
                                         float& kt2, int& it2) {
    bool up = ((e & k) == 0);
    bool amLow = ((e & j) == 0);
    float pks = __shfl_xor_sync(0xFFFFFFFFu, ks, j);
    int   pis = __shfl_xor_sync(0xFFFFFFFFu, is, j);
    float pkt = __shfl_xor_sync(0xFFFFFFFFu, kt2, j);
    int   pit = __shfl_xor_sync(0xFFFFFFFFu, it2, j);
    bool c1 = amLow ? ((ks > pks) == up) : ((pks > ks) == up);
    if (c1) { ks = pks; is = pis; }
    bool c2 = amLow ? ((kt2 > pkt) == up) : ((pkt > kt2) == up);
    if (c2) { kt2 = pkt; it2 = pit; }
}

// ---------------------------------------------------------------------------
// kS: one block per (b,h), 1024 threads. Folds out_W hi/lo split. Shuffle
//     bitonic sorts, warp scans, Z, 17 buckets, 16 chunk sums, prefixes.
// ---------------------------------------------------------------------------
#define S_SV    0
#define S_TV    1024
#define S_SIDX  2048
#define S_TPI   3072
#define S_SCANA 4096
#define S_SCANB 6144
#define S_WAS   8192
#define S_WBS   9216
#define S_PARTA 10240
#define S_PARTB 11264
#define S_BOFF  12288   /* 32 ints */
#define S_CNT   12320   /* 32 ints */
#define KS_FLOATS 12352
#define KS_SMEM (KS_FLOATS * 4)

__global__ __launch_bounds__(1024) void kS_all(const float* __restrict__ oW) {
    extern __shared__ float sm[];
    float* sv    = sm + S_SV;
    float* tv    = sm + S_TV;
    int*   sidx  = (int*)(sm + S_SIDX);
    int*   tpi   = (int*)(sm + S_TPI);
    float* scanA = sm + S_SCANA;
    float* scanB = sm + S_SCANB;
    float* wAs   = sm + S_WAS;
    float* wBs   = sm + S_WBS;
    float* partA = sm + S_PARTA;
    float* partB = sm + S_PARTB;
    int*   boff  = (int*)(sm + S_BOFF);
    int*   cnt   = (int*)(sm + S_CNT);

    int tid = threadIdx.x;
    int lane = tid & 31, wrp = tid >> 5;
    int bh = blockIdx.x;
    int b = bh >> 3, hh = bh & 7;
    int base = bh * NN;

    // folded kW: out_W hi/lo split
    {
        int i = bh * 1024 + tid;
        if (i < CC * DD) {
            float v = oW[i];
            __nv_bfloat16 hi = __float2bfloat16_rn(v);
            g_oWH[i] = hi;
            g_oWL[i] = __float2bfloat16_rn(v - __bfloat162float(hi));
        }
    }

    float s0 = g_s[base + tid];
    sv[tid] = s0;  sidx[tid] = tid;
    tv[tid] = g_t[base + tid];  tpi[tid] = tid;
    if (tid < 32) { boff[tid] = 0; cnt[tid] = 0; }
    __syncthreads();

    // ---- bitonic sort, dual arrays; all j<=16 phases in registers ----
    {
        float ksv = sv[tid]; int kis = sidx[tid];
        float ktv = tv[tid]; int kit = tpi[tid];
#pragma unroll
        for (int k = 2; k <= 32; k <<= 1)
#pragma unroll
            for (int j = k >> 1; j > 0; j >>= 1)
                shfl_cex(tid, k, j, ksv, kis, ktv, kit);
        sv[tid] = ksv; sidx[tid] = kis; tv[tid] = ktv; tpi[tid] = kit;
        __syncthreads();
        for (int k = 64; k <= 1024; k <<= 1) {
            for (int j = k >> 1; j >= 32; j >>= 1) {
                int ixj = tid ^ j;
                if (ixj > tid) {
                    bool up = ((tid & k) == 0);
                    float av = sv[tid], bq = sv[ixj];
                    if ((av > bq) == up) {
                        sv[tid] = bq; sv[ixj] = av;
                        int tmp = sidx[tid]; sidx[tid] = sidx[ixj]; sidx[ixj] = tmp;
                    }
                    float at = tv[tid], bt = tv[ixj];
                    if ((at > bt) == up) {
                        tv[tid] = bt; tv[ixj] = at;
                        int tmp = tpi[tid]; tpi[tid] = tpi[ixj]; tpi[ixj] = tmp;
                    }
                }
                __syncthreads();
            }
            ksv = sv[tid]; kis = sidx[tid]; ktv = tv[tid]; kit = tpi[tid];
#pragma unroll
            for (int j = 16; j > 0; j >>= 1)
                shfl_cex(tid, k, j, ksv, kis, ktv, kit);
            sv[tid] = ksv; sidx[tid] = kis; tv[tid] = ktv; tpi[tid] = kit;
            __syncthreads();
        }
    }

    // ---- inclusive scans of es/es01 in s-sorted order (warp shuffles) ----
    {
        int io = sidx[tid];
        float aA = g_es[base + io];
        float aB = g_es01[base + io];
#pragma unroll
        for (int d = 1; d < 32; d <<= 1) {
            float uA = __shfl_up_sync(0xFFFFFFFFu, aA, d);
            float uB = __shfl_up_sync(0xFFFFFFFFu, aB, d);
            if (lane >= d) { aA += uA; aB += uB; }
        }
        if (lane == 31) { scanA[1024 + wrp] = aA; scanB[1024 + wrp] = aB; }
        __syncthreads();
        if (wrp == 0) {
            float wa = scanA[1024 + lane], wb = scanB[1024 + lane];
#pragma unroll
            for (int d = 1; d < 32; d <<= 1) {
                float uA = __shfl_up_sync(0xFFFFFFFFu, wa, d);
                float uB = __shfl_up_sync(0xFFFFFFFFu, wb, d);
                if (lane >= d) { wa += uA; wb += uB; }
            }
            scanA[1024 + lane] = wa; scanB[1024 + lane] = wb;
        }
        __syncthreads();
        float offA = wrp ? scanA[1024 + wrp - 1] : 0.f;
        float offB = wrp ? scanB[1024 + wrp - 1] : 0.f;
        scanA[tid] = aA + offA;
        scanB[tid] = aB + offB;
    }
    __syncthreads();
    const float* inclA = scanA;
    const float* inclB = scanB;
    float ES_tot = inclA[1023];

    {
        int cpr = ub1024(sv, -tv[tid]);
        int jo = tpi[tid];
        float et = g_et[base + jo], et01 = g_et01[base + jo];
        float pa = cpr ? inclA[cpr - 1] : 0.f;
        float pb = cpr ? inclB[cpr - 1] : 0.f;
        float rz = 1.f / (et * (ES_tot - pa) + et01 * pb);
        float wa = et * rz, wb = et01 * rz;
        wAs[tid] = wa;  wBs[tid] = wb;
        g_wA[base + tid] = wa;
        g_wB[base + tid] = wb;
        g_tpi[base + tid] = jo;
    }

    {
        int c = ub1024(tv, -s0);
        g_ci[base + tid] = c;
        int bu = (c == 0) ? 0 : (1 + ((c - 1) >> 6));   // 17 buckets
        atomicAdd(&boff[bu + 1], 1);
    }
    __syncthreads();

    // chunk sums: one thread per (ch, d), 16 x 64 = 1024
    {
        int ch = tid >> 6;
        int d = tid & 63;
        int m0 = ch * 64;
        float pa = 0.f, pb = 0.f;
#pragma unroll 4
        for (int q = 0; q < 64; q++) {
            int m = m0 + q;
            float v = g_Wh[(size_t)(b * NN + tpi[m]) * CC + hh * DD + d];
            pa = fmaf(wAs[m], v, pa);
            pb = fmaf(wBs[m], v, pb);
        }
        partA[ch * 64 + d] = pa;
        partB[ch * 64 + d] = pb;
    }
    __syncthreads();

    if (tid == 0)
        for (int q = 1; q <= 17; q++) boff[q] += boff[q - 1];
    __syncthreads();

    {
        int c = g_ci[base + tid];
        int bu = (c == 0) ? 0 : (1 + ((c - 1) >> 6));
        int pos = boff[bu] + atomicAdd(&cnt[bu], 1);
        g_qord[base + pos] = tid;
    }
    if (tid < 32) g_bofG[bh * 32 + tid] = boff[tid];

    if (tid < 64) {
        int d = tid;
        float pa = 0.f, pb = 0.f;
#pragma unroll
        for (int ch = 0; ch < 16; ch++) {
            int o = (bh * 16 + ch) * 64 + d;
            g_prA[o] = pa;  g_prB[o] = pb;
            pa += partA[ch * 64 + d];
            pb += partB[ch * 64 + d];
        }
        g_TotA[bh * 64 + d] = pa;
    }
}

// ---------------------------------------------------------------------------
// kD: 64-wide chunks. grid 1024 = bh*16+ch, 256 threads, ~63 KB smem
//     -> 3 CTA/SM.
// ---------------------------------------------------------------------------
#define D_STAGE  0        /* 64 x 64 */
#define D_LOCA   4096
#define D_LOCB   8192
#define D_WA     12288
#define D_WB     12352
#define D_TOT    12416
#define D_PRA    12480
#define D_PRB    12544
#define D_TPI    12608    /* 64 ints */
#define D_QPK    12672    /* 1024 ints */
#define D_QES    13696
#define D_QES01  14720
#define KD_FLOATS 15744
#define KD_SMEM (KD_FLOATS * 4)

__device__ __forceinline__ void store_hilo(size_t o, float val) {
    __nv_bfloat16 hi = __float2bfloat16_rn(val);
    g_hpH[o] = hi;
    g_hpL[o] = __float2bfloat16_rn(val - __bfloat162float(hi));
}

__global__ __launch_bounds__(256) void kD_apply() {
    extern __shared__ float sm[];
    float* stage = sm + D_STAGE;
    float* locA = sm + D_LOCA;
    float* locB = sm + D_LOCB;
    float* wAs  = sm + D_WA;
    float* wBs  = sm + D_WB;
    float* Tot  = sm + D_TOT;
    float* prA  = sm + D_PRA;
    float* prB  = sm + D_PRB;
    int*   tpis = (int*)(sm + D_TPI);
    int*   qpk  = (int*)(sm + D_QPK);
    float* qes  = sm + D_QES;
    float* qes01= sm + D_QES01;

    int tid = threadIdx.x;
    int bh = blockIdx.x >> 4, ch = blockIdx.x & 15;
    int b = bh >> 3, hh = bh & 7;
    int base = bh * NN;
    int cbase = base + ch * 64;

    int qs = (ch == 0) ? g_bofG[bh * 32 + 0] : g_bofG[bh * 32 + ch + 1];
    int qe = g_bofG[bh * 32 + ch + 2];
    int nq = qe - qs;

    if (tid < 64) {
        wAs[tid] = g_wA[cbase + tid];
        wBs[tid] = g_wB[cbase + tid];
        tpis[tid] = g_tpi[cbase + tid];
    } else if (tid < 128) {
        Tot[tid - 64] = g_TotA[bh * 64 + (tid - 64)];
    } else if (tid < 192) {
        prA[tid - 128] = g_prA[(bh * 16 + ch) * 64 + (tid - 128)];
    } else {
        prB[tid - 192] = g_prB[(bh * 16 + ch) * 64 + (tid - 192)];
    }
    __syncthreads();

#pragma unroll
    for (int p = 0; p < 4; p++) {
        int idx = p * 256 + tid;
        int m = idx >> 4, f4 = idx & 15;
        *(float4*)&stage[m * 64 + f4 * 4] =
            *(const float4*)&g_Wh[(size_t)(b * NN + tpis[m]) * CC + hh * DD + f4 * 4];
    }
    __syncthreads();

    if (tid < 128) {
        int half = tid >> 6, d = tid & 63;
        const float* w = half ? wBs : wAs;
        float* loc = half ? locB : locA;
        float run = 0.f;
#pragma unroll 8
        for (int m = 0; m < 64; m++) {
            run = fmaf(w[m], stage[m * 64 + d], run);
            loc[m * 64 + d] = run;
        }
    } else {
        int t2 = tid - 128;
        for (int q = qs + t2; q < qe; q += 128) {
            int i = g_qord[base + q];
            int c = g_ci[base + i];
            int off = c - ch * 64 - 1;
            qpk[q - qs] = i | ((off + 1) << 16);
            qes[q - qs]   = g_es[base + i];
            qes01[q - qs] = g_es01[base + i];
        }
    }
    __syncthreads();

    {
        int qg = tid >> 6, d = tid & 63;
        float totd = Tot[d], prad = prA[d], prbd = prB[d];
        float tma = totd - prad;
        for (int q = qg; q < nq; q += 4) {
            int pk = qpk[q];
            int i = pk & 0xFFFF;
            int offp = pk >> 16;
            float es = qes[q];
            float val;
            if (offp == 0) {
                val = es * totd;
            } else {
                int off = offp - 1;
                val = es * (tma - locA[off * 64 + d])
                    + qes01[q] * (prbd + locB[off * 64 + d]);
            }
            store_hilo((size_t)(b * NN + i) * CC + hh * DD + d, val);
        }
    }
}

// ---------------------------------------------------------------------------
// k5m: out = h' @ out_W + b via mma.sync bf16 hi/lo, cp.async pipeline.
// All operands streamed per 64-K chunk. Slot = Ah(32x72) Al Bh(64x72) Bl
// = 27648 B; 4 slots = 110.6 KB -> 2 CTA/SM. Depth-3 pipeline, 1 sync/chunk.
// ---------------------------------------------------------------------------
#define K5_SLOT 27648
#define K5_SMEM (4 * K5_SLOT)

__global__ __launch_bounds__(256) void k5m(const float* __restrict__ ob,
                                           float* __restrict__ out) {
    extern __shared__ __nv_bfloat16 smb[];
    int tid = threadIdx.x, lane = tid & 31, w = tid >> 5;
    int mi = w & 1, nc = w >> 1;
    int r0 = blockIdx.x * 32;
    int arow = tid >> 3, ag = tid & 7;
    uint32_t sbase = smem_u32(smb);

    const __nv_bfloat16* hpHrow = g_hpH + (size_t)(r0 + arow) * CC + ag * 8;
    const __nv_bfloat16* hpLrow = g_hpL + (size_t)(r0 + arow) * CC + ag * 8;

#define K5_ISSUE(c) do {                                                      \
        int _c = (c);                                                         \
        uint32_t _sb = sbase + (uint32_t)(_c & 3) * K5_SLOT;                  \
        uint32_t _da = _sb + (uint32_t)(arow * 72 + ag * 8) * 2;              \
        CP16(_da,        hpHrow + _c * 64);                                   \
        CP16(_da + 4608, hpLrow + _c * 64);                                   \
        _Pragma("unroll")                                                     \
        for (int _p = 0; _p < 2; _p++) {                                      \
            int _idx = _p * 256 + tid;                                        \
            int _row = _idx >> 3, _g = _idx & 7;                              \
            uint32_t _db = _sb + 9216 + (uint32_t)(_row * 72 + _g * 8) * 2;   \
            CP16(_db,        &g_oWH[(size_t)(_c * 64 + _row) * 64 + _g * 8]); \
            CP16(_db + 9216, &g_oWL[(size_t)(_c * 64 + _row) * 64 + _g * 8]); \
        }                                                                     \
        CP_COMMIT();                                                          \
    } while (0)

    K5_ISSUE(0);
    K5_ISSUE(1);
    K5_ISSUE(2);

    uint32_t aoff = (uint32_t)(((((lane >> 3) & 1) * 8 + (lane & 7)) + mi * 16) * 72
                               + (lane >> 4) * 8) * 2;
    uint32_t bB = (uint32_t)((lane & 15) * 72 + (lane >> 4) * 8) * 2
                  + (uint32_t)nc * 32;

    float acc[2][4] = {};

    for (int c = 0; c < 8; c++) {
        CP_WAIT2();
        __syncthreads();
        if (c + 3 < 8) { K5_ISSUE(c + 3); } else { CP_COMMIT(); }

        uint32_t sb = sbase + (uint32_t)(c & 3) * K5_SLOT;
        uint32_t aAh = sb + aoff;
        uint32_t aAl = aAh + 4608;
        uint32_t aBh = sb + 9216 + bB;
        uint32_t aBl = aBh + 9216;
#pragma unroll
        for (int kk = 0; kk < 4; kk++) {
            uint32_t ka = (uint32_t)(kk * 32);
            uint32_t rb = (uint32_t)(kk * 16 * 144);
            uint32_t ah0, ah1, ah2, ah3, al0, al1, al2, al3;
            uint32_t bh0, bh1, bh2, bh3, bl0, bl1, bl2, bl3;
            LDSM4(ah0, ah1, ah2, ah3, aAh + ka);
            LDSM4(al0, al1, al2, al3, aAl + ka);
            LDSM_T4(bh0, bh1, bh2, bh3, aBh + rb);
            LDSM_T4(bl0, bl1, bl2, bl3, aBl + rb);
            MMA16816(acc[0][0], acc[0][1], acc[0][2], acc[0][3],
                     ah0, ah1, ah2, ah3, bh0, bh1);
            MMA16816(acc[1][0], acc[1][1], acc[1][2], acc[1][3],
                     ah0, ah1, ah2, ah3, bh2, bh3);
            MMA16816(acc[0][0], acc[0][1], acc[0][2], acc[0][3],
                     ah0, ah1, ah2, ah3, bl0, bl1);
            MMA16816(acc[1][0], acc[1][1], acc[1][2], acc[1][3],
                     ah0, ah1, ah2, ah3, bl2, bl3);
            MMA16816(acc[0][0], acc[0][1], acc[0][2], acc[0][3],
                     al0, al1, al2, al3, bh0, bh1);
            MMA16816(acc[1][0], acc[1][1], acc[1][2], acc[1][3],
                     al0, al1, al2, al3, bh2, bh3);
        }
    }

    int gr = lane >> 2, c2 = (lane & 3) * 2;
    int row0 = r0 + mi * 16 + gr;
#pragma unroll
    for (int t = 0; t < 2; t++) {
        int col = nc * 16 + t * 8 + c2;
        float b0 = ob[col], b1 = ob[col + 1];
        float2 o0 = {acc[t][0] + b0, acc[t][1] + b1};
        float2 o1 = {acc[t][2] + b0, acc[t][3] + b1};
        *(float2*)&out[(size_t)row0 * DD + col] = o0;
        *(float2*)&out[(size_t)(row0 + 8) * DD + col] = o1;
    }
#undef K5_ISSUE
}

// ---------------------------------------------------------------------------
extern "C" void kernel_launch(void* const* d_in, const int* in_sizes, int n_in,
                              void* d_out, int out_size) {
    const float* h    = (const float*)d_in[0];
    const float* W    = (const float*)d_in[2];
    const float* a    = (const float*)d_in[3];
    const float* oW   = (const float*)d_in[4];
    const float* ob   = (const float*)d_in[5];
    float* out = (float*)d_out;

    cudaFuncSetAttribute(kS_all, cudaFuncAttributeMaxDynamicSharedMemorySize,
                         KS_SMEM);
    cudaFuncSetAttribute(kD_apply, cudaFuncAttributeMaxDynamicSharedMemorySize,
                         KD_SMEM);
    cudaFuncSetAttribute(k5m, cudaFuncAttributeMaxDynamicSharedMemorySize,
                         K5_SMEM);

    k1x<<<dim3(HH, (BB*NN)/64), 256>>>(h, W, a);
    kS_all<<<BB*HH, 1024, KS_SMEM>>>(oW);
    kD_apply<<<BB*HH*16, 256, KD_SMEM>>>();
    k5m<<<(BB*NN)/32, 256, K5_SMEM>>>(ob, out);
}

// round 15
// speedup vs baseline: 1.2516x; 1.0278x over previous
#include <cuda_runtime.h>
#include <cuda_bf16.h>
#include <cstdint>
#include <cstddef>

#define BB 8
#define NN 1024
#define HH 8
#define DD 64
#define CC (HH*DD)   // 512

// Scratch
__device__ __nv_bfloat16 g_hpH[BB*NN*CC];
__device__ __nv_bfloat16 g_hpL[BB*NN*CC];
__device__ __nv_bfloat16 g_oWH[CC*DD];
__device__ __nv_bfloat16 g_oWL[CC*DD];
__device__ float g_s   [BB*HH*NN];
__device__ float g_t   [BB*HH*NN];
__device__ float g_es  [BB*HH*NN];
__device__ float g_es01[BB*HH*NN];
__device__ float g_et  [BB*HH*NN];
__device__ float g_et01[BB*HH*NN];
__device__ float g_Wh[BB*NN*CC];
// sort/scan pipeline scratch (16 chunks of 64)
__device__ int   g_tpi [BB*HH*NN];
__device__ float g_wA  [BB*HH*NN];
__device__ float g_wB  [BB*HH*NN];
__device__ int   g_ci  [BB*HH*NN];
__device__ int   g_qord[BB*HH*NN];
__device__ int   g_bofG[BB*HH*32];
__device__ float g_prA [BB*HH*16*64];
__device__ float g_prB [BB*HH*16*64];
__device__ float g_TotA[BB*HH*64];

__device__ __forceinline__ uint32_t smem_u32(const void* p) {
    uint32_t a;
    asm("{ .reg .u64 t; cvta.to.shared.u64 t, %1; cvt.u32.u64 %0, t; }" : "=r"(a) : "l"(p));
    return a;
}
// PDL: wait for the programmatically-linked predecessor grid's writes
#define GRID_DEP_WAIT() asm volatile("griddepcontrol.wait;" ::: "memory")

#define LDSM4(r0, r1, r2, r3, addr) \
    asm volatile("ldmatrix.sync.aligned.m8n8.x4.shared.b16 {%0,%1,%2,%3}, [%4];" \
                 : "=r"(r0), "=r"(r1), "=r"(r2), "=r"(r3) : "r"(addr))
#define LDSM_T4(r0, r1, r2, r3, addr) \
    asm volatile("ldmatrix.sync.aligned.m8n8.x4.trans.shared.b16 {%0,%1,%2,%3}, [%4];" \
                 : "=r"(r0), "=r"(r1), "=r"(r2), "=r"(r3) : "r"(addr))
#define MMA16816(d0,d1,d2,d3, a0,a1,a2,a3, b0,b1) \
    asm volatile("mma.sync.aligned.m16n8k16.row.col.f32.bf16.bf16.f32 " \
                 "{%0,%1,%2,%3}, {%4,%5,%6,%7}, {%8,%9}, {%0,%1,%2,%3};" \
                 : "+f"(d0), "+f"(d1), "+f"(d2), "+f"(d3) \
                 : "r"(a0), "r"(a1), "r"(a2), "r"(a3), "r"(b0), "r"(b1))
#define CP16(dst, src) \
    asm volatile("cp.async.cg.shared.global [%0], [%1], 16;" :: "r"(dst), "l"(src))
#define CP_COMMIT() asm volatile("cp.async.commit_group;" ::: "memory")
#define CP_WAIT2()  asm volatile("cp.async.wait_group 2;" ::: "memory")

// ---------------------------------------------------------------------------
// k1x: Wh = h @ W (64-row x one-head tile per block) fused with s/t/exp.
// ---------------------------------------------------------------------------
__global__ __launch_bounds__(256) void k1x(const float* __restrict__ h,
                                           const float* __restrict__ W,
                                           const float* __restrict__ a) {
    __shared__ __align__(16) float As[64][68];   // [row][k]
    __shared__ __align__(16) float Bs[64][68];   // [k][col]
    __shared__ float as[128];
    __shared__ float sred[64][17], tred[64][17];
    int tid = threadIdx.x;
    int hh = blockIdx.x;
    int r0 = blockIdx.y * 64;
    int c0 = hh * 64;
    if (tid < 128) as[tid] = a[tid];
#pragma unroll
    for (int p = 0; p < 4; p++) {
        int idx = p * 256 + tid;
        int r = idx >> 4, k4 = idx & 15;
        *(float4*)&As[r][k4*4] = *(const float4*)&h[(size_t)(r0 + r) * 64 + k4*4];
        *(float4*)&Bs[r][k4*4] = *(const float4*)&W[(size_t)r * CC + c0 + k4*4];
    }
    __syncthreads();
    int tx = tid & 15, ty = tid >> 4;
    float acc[4][4] = {};
#pragma unroll
    for (int k4 = 0; k4 < 16; k4++) {
        float4 a4[4], b4[4];
#pragma unroll
        for (int r = 0; r < 4; r++) a4[r] = *(const float4*)&As[ty*4+r][k4*4];
#pragma unroll
        for (int kk = 0; kk < 4; kk++) b4[kk] = *(const float4*)&Bs[k4*4+kk][tx*4];
#pragma unroll
        for (int kk = 0; kk < 4; kk++) {
            float ak[4] = { kk==0?a4[0].x:kk==1?a4[0].y:kk==2?a4[0].z:a4[0].w,
                            kk==0?a4[1].x:kk==1?a4[1].y:kk==2?a4[1].z:a4[1].w,
                            kk==0?a4[2].x:kk==1?a4[2].y:kk==2?a4[2].z:a4[2].w,
                            kk==0?a4[3].x:kk==1?a4[3].y:kk==2?a4[3].z:a4[3].w };
            float bk[4] = { b4[kk].x, b4[kk].y, b4[kk].z, b4[kk].w };
#pragma unroll
            for (int r = 0; r < 4; r++)
#pragma unroll
                for (int c = 0; c < 4; c++)
                    acc[r][c] = fmaf(ak[r], bk[c], acc[r][c]);
        }
    }
#pragma unroll
    for (int r = 0; r < 4; r++) {
        float4 o = {acc[r][0], acc[r][1], acc[r][2], acc[r][3]};
        *(float4*)&g_Wh[(size_t)(r0 + ty*4 + r) * CC + c0 + tx*4] = o;
        float ps = 0.f, pt = 0.f;
#pragma unroll
        for (int c = 0; c < 4; c++) {
            ps = fmaf(acc[r][c], as[tx*4 + c], ps);
            pt = fmaf(acc[r][c], as[64 + tx*4 + c], pt);
        }
        sred[ty*4 + r][tx] = ps;
        tred[ty*4 + r][tx] = pt;
    }
    __syncthreads();
    if (tid < 64) {
        float s = 0.f, t = 0.f;
#pragma unroll
        for (int x = 0; x < 16; x++) { s += sred[tid][x]; t += tred[tid][x]; }
        int gr = r0 + tid;
        int b = gr >> 10, n = gr & (NN - 1);
        int o = (b * HH + hh) * NN + n;
        g_s[o] = s;                 g_t[o] = t;
        g_es[o]   = __expf(s);      g_es01[o] = __expf(0.01f * s);
        g_et[o]   = __expf(t);      g_et01[o] = __expf(0.01f * t);
    }
}

// ---------------------------------------------------------------------------
__device__ __forceinline__ int ub1024(const float* __restrict__ arr, float key) {
    int lo = 0, hi = 1024;
    while (lo < hi) {
        int mid = (lo + hi) >> 1;
        if (arr[mid] <= key) lo = mid + 1; else hi = mid;
    }
    return lo;
}

__device__ __forceinline__ void shfl_cex(int e, int k, int j,
                                         float& ks, int& is,
                                         float& kt2, int& it2) {
    bool up = ((e & k) == 0);
    bool amLow = ((e & j) == 0);
    float pks = __shfl_xor_sync(0xFFFFFFFFu, ks, j);
    int   pis = __shfl_xor_sync(0xFFFFFFFFu, is, j);
    float pkt = __shfl_xor_sync(0xFFFFFFFFu, kt2, j);
    int   pit = __shfl_xor_sync(0xFFFFFFFFu, it2, j);
    bool c1 = amLow ? ((ks > pks) == up) : ((pks > ks) == up);
    if (c1) { ks = pks; is = pis; }
    bool c2 = amLow ? ((kt2 > pkt) == up) : ((pkt > kt2) == up);
    if (c2) { kt2 = pkt; it2 = pit; }
}

// ---------------------------------------------------------------------------
// kS: one block per (b,h), 1024 threads. Folds out_W hi/lo split (independent
//     of k1x -> done BEFORE the grid-dep wait). Shuffle bitonic sorts, warp
//     scans, Z, 17 buckets, 16 chunk sums, coarse prefixes.
// ---------------------------------------------------------------------------
#define S_SV    0
#define S_TV    1024
#define S_SIDX  2048
#define S_TPI   3072
#define S_SCANA 4096
#define S_SCANB 6144
#define S_WAS   8192
#define S_WBS   9216
#define S_PARTA 10240
#define S_PARTB 11264
#define S_BOFF  12288   /* 32 ints */
#define S_CNT   12320   /* 32 ints */
#define KS_FLOATS 12352
#define KS_SMEM (KS_FLOATS * 4)

__global__ __launch_bounds__(1024) void kS_all(const float* __restrict__ oW) {
    extern __shared__ float sm[];
    float* sv    = sm + S_SV;
    float* tv    = sm + S_TV;
    int*   sidx  = (int*)(sm + S_SIDX);
    int*   tpi   = (int*)(sm + S_TPI);
    float* scanA = sm + S_SCANA;
    float* scanB = sm + S_SCANB;
    float* wAs   = sm + S_WAS;
    float* wBs   = sm + S_WBS;
    float* partA = sm + S_PARTA;
    float* partB = sm + S_PARTB;
    int*   boff  = (int*)(sm + S_BOFF);
    int*   cnt   = (int*)(sm + S_CNT);

    int tid = threadIdx.x;
    int lane = tid & 31, wrp = tid >> 5;
    int bh = blockIdx.x;
    int b = bh >> 3, hh = bh & 7;
    int base = bh * NN;

    // folded kW: out_W hi/lo split — reads only the kernel INPUT oW, so it
    // runs before the PDL wait, overlapping k1x's tail.
    {
        int i = bh * 1024 + tid;
        if (i < CC * DD) {
            float v = oW[i];
            __nv_bfloat16 hi = __float2bfloat16_rn(v);
            g_oWH[i] = hi;
            g_oWL[i] = __float2bfloat16_rn(v - __bfloat162float(hi));
        }
    }
    if (tid < 32) { boff[tid] = 0; cnt[tid] = 0; }

    GRID_DEP_WAIT();   // k1x's g_s/g_t/g_es... now visible

    float s0 = g_s[base + tid];
    sv[tid] = s0;  sidx[tid] = tid;
    tv[tid] = g_t[base + tid];  tpi[tid] = tid;
    __syncthreads();

    // ---- bitonic sort, dual arrays; all j<=16 phases in registers ----
    {
        float ksv = sv[tid]; int kis = sidx[tid];
        float ktv = tv[tid]; int kit = tpi[tid];
#pragma unroll
        for (int k = 2; k <= 32; k <<= 1)
#pragma unroll
            for (int j = k >> 1; j > 0; j >>= 1)
                shfl_cex(tid, k, j, ksv, kis, ktv, kit);
        sv[tid] = ksv; sidx[tid] = kis; tv[tid] = ktv; tpi[tid] = kit;
        __syncthreads();
        for (int k = 64; k <= 1024; k <<= 1) {
            for (int j = k >> 1; j >= 32; j >>= 1) {
                int ixj = tid ^ j;
                if (ixj > tid) {
                    bool up = ((tid & k) == 0);
                    float av = sv[tid], bq = sv[ixj];
                    if ((av > bq) == up) {
                        sv[tid] = bq; sv[ixj] = av;
                        int tmp = sidx[tid]; sidx[tid] = sidx[ixj]; sidx[ixj] = tmp;
                    }
                    float at = tv[tid], bt = tv[ixj];
                    if ((at > bt) == up) {
                        tv[tid] = bt; tv[ixj] = at;
                        int tmp = tpi[tid]; tpi[tid] = tpi[ixj]; tpi[ixj] = tmp;
                    }
                }
                __syncthreads();
            }
            ksv = sv[tid]; kis = sidx[tid]; ktv = tv[tid]; kit = tpi[tid];
#pragma unroll
            for (int j = 16; j > 0; j >>= 1)
                shfl_cex(tid, k, j, ksv, kis, ktv, kit);
            sv[tid] = ksv; sidx[tid] = kis; tv[tid] = ktv; tpi[tid] = kit;
            __syncthreads();
        }
    }

    // ---- inclusive scans of es/es01 in s-sorted order (warp shuffles) ----
    {
        int io = sidx[tid];
        float aA = g_es[base + io];
        float aB = g_es01[base + io];
#pragma unroll
        for (int d = 1; d < 32; d <<= 1) {
            float uA = __shfl_up_sync(0xFFFFFFFFu, aA, d);
            float uB = __shfl_up_sync(0xFFFFFFFFu, aB, d);
            if (lane >= d) { aA += uA; aB += uB; }
        }
        if (lane == 31) { scanA[1024 + wrp] = aA; scanB[1024 + wrp] = aB; }
        __syncthreads();
        if (wrp == 0) {
            float wa = scanA[1024 + lane], wb = scanB[1024 + lane];
#pragma unroll
            for (int d = 1; d < 32; d <<= 1) {
                float uA = __shfl_up_sync(0xFFFFFFFFu, wa, d);
                float uB = __shfl_up_sync(0xFFFFFFFFu, wb, d);
                if (lane >= d) { wa += uA; wb += uB; }
            }
            scanA[1024 + lane] = wa; scanB[1024 + lane] = wb;
        }
        __syncthreads();
        float offA = wrp ? scanA[1024 + wrp - 1] : 0.f;
        float offB = wrp ? scanB[1024 + wrp - 1] : 0.f;
        scanA[tid] = aA + offA;
        scanB[tid] = aB + offB;
    }
    __syncthreads();
    const float* inclA = scanA;
    const float* inclB = scanB;
    float ES_tot = inclA[1023];

    {
        int cpr = ub1024(sv, -tv[tid]);
        int jo = tpi[tid];
        float et = g_et[base + jo], et01 = g_et01[base + jo];
        float pa = cpr ? inclA[cpr - 1] : 0.f;
        float pb = cpr ? inclB[cpr - 1] : 0.f;
        float rz = 1.f / (et * (ES_tot - pa) + et01 * pb);
        float wa = et * rz, wb = et01 * rz;
        wAs[tid] = wa;  wBs[tid] = wb;
        g_wA[base + tid] = wa;
        g_wB[base + tid] = wb;
        g_tpi[base + tid] = jo;
    }

    {
        int c = ub1024(tv, -s0);
        g_ci[base + tid] = c;
        int bu = (c == 0) ? 0 : (1 + ((c - 1) >> 6));   // 17 buckets
        atomicAdd(&boff[bu + 1], 1);
    }
    __syncthreads();

    // chunk sums: one thread per (ch, d), 16 x 64 = 1024
    {
        int ch = tid >> 6;
        int d = tid & 63;
        int m0 = ch * 64;
        float pa = 0.f, pb = 0.f;
#pragma unroll 4
        for (int q = 0; q < 64; q++) {
            int m = m0 + q;
            float v = g_Wh[(size_t)(b * NN + tpi[m]) * CC + hh * DD + d];
            pa = fmaf(wAs[m], v, pa);
            pb = fmaf(wBs[m], v, pb);
        }
        partA[ch * 64 + d] = pa;
        partB[ch * 64 + d] = pb;
    }
    __syncthreads();

    if (tid == 0)
        for (int q = 1; q <= 17; q++) boff[q] += boff[q - 1];
    __syncthreads();

    {
        int c = g_ci[base + tid];
        int bu = (c == 0) ? 0 : (1 + ((c - 1) >> 6));
        int pos = boff[bu] + atomicAdd(&cnt[bu], 1);
        g_qord[base + pos] = tid;
    }
    if (tid < 32) g_bofG[bh * 32 + tid] = boff[tid];

    if (tid < 64) {
        int d = tid;
        float pa = 0.f, pb = 0.f;
#pragma unroll
        for (int ch = 0; ch < 16; ch++) {
            int o = (bh * 16 + ch) * 64 + d;
            g_prA[o] = pa;  g_prB[o] = pb;
            pa += partA[ch * 64 + d];
            pb += partB[ch * 64 + d];
        }
        g_TotA[bh * 64 + d] = pa;
    }
}

// ---------------------------------------------------------------------------
// kD: 64-wide chunks. grid 1024 = bh*16+ch, 256 threads, ~63 KB smem
//     -> 3 CTA/SM.
// ---------------------------------------------------------------------------
#define D_STAGE  0        /* 64 x 64 */
#define D_LOCA   4096
#define D_LOCB   8192
#define D_WA     12288
#define D_WB     12352
#define D_TOT    12416
#define D_PRA    12480
#define D_PRB    12544
#define D_TPI    12608    /* 64 ints */
#define D_QPK    12672    /* 1024 ints */
#define D_QES    13696
#define D_QES01  14720
#define KD_FLOATS 15744
#define KD_SMEM (KD_FLOATS * 4)

__device__ __forceinline__ void store_hilo(size_t o, float val) {
    __nv_bfloat16 hi = __float2bfloat16_rn(val);
    g_hpH[o] = hi;
    g_hpL[o] = __float2bfloat16_rn(val - __bfloat162float(hi));
}

__global__ __launch_bounds__(256) void kD_apply() {
    extern __shared__ float sm[];
    float* stage = sm + D_STAGE;
    float* locA = sm + D_LOCA;
    float* locB = sm + D_LOCB;
    float* wAs  = sm + D_WA;
    float* wBs  = sm + D_WB;
    float* Tot  = sm + D_TOT;
    float* prA  = sm + D_PRA;
    float* prB  = sm + D_PRB;
    int*   tpis = (int*)(sm + D_TPI);
    int*   qpk  = (int*)(sm + D_QPK);
    float* qes  = sm + D_QES;
    float* qes01= sm + D_QES01;

    int tid = threadIdx.x;
    int bh = blockIdx.x >> 4, ch = blockIdx.x & 15;
    int b = bh >> 3, hh = bh & 7;
    int base = bh * NN;
    int cbase = base + ch * 64;

    GRID_DEP_WAIT();   // kS outputs now visible

    int qs = (ch == 0) ? g_bofG[bh * 32 + 0] : g_bofG[bh * 32 + ch + 1];
    int qe = g_bofG[bh * 32 + ch + 2];
    int nq = qe - qs;

    if (tid < 64) {
        wAs[tid] = g_wA[cbase + tid];
        wBs[tid] = g_wB[cbase + tid];
        tpis[tid] = g_tpi[cbase + tid];
    } else if (tid < 128) {
        Tot[tid - 64] = g_TotA[bh * 64 + (tid - 64)];
    } else if (tid < 192) {
        prA[tid - 128] = g_prA[(bh * 16 + ch) * 64 + (tid - 128)];
    } else {
        prB[tid - 192] = g_prB[(bh * 16 + ch) * 64 + (tid - 192)];
    }
    __syncthreads();

#pragma unroll
    for (int p = 0; p < 4; p++) {
        int idx = p * 256 + tid;
        int m = idx >> 4, f4 = idx & 15;
        *(float4*)&stage[m * 64 + f4 * 4] =
            *(const float4*)&g_Wh[(size_t)(b * NN + tpis[m]) * CC + hh * DD + f4 * 4];
    }
    __syncthreads();

    if (tid < 128) {
        int half = tid >> 6, d = tid & 63;
        const float* w = half ? wBs : wAs;
        float* loc = half ? locB : locA;
        float run = 0.f;
#pragma unroll 8
        for (int m = 0; m < 64; m++) {
            run = fmaf(w[m], stage[m * 64 + d], run);
            loc[m * 64 + d] = run;
        }
    } else {
        int t2 = tid - 128;
        for (int q = qs + t2; q < qe; q += 128) {
            int i = g_qord[base + q];
            int c = g_ci[base + i];
            int off = c - ch * 64 - 1;
            qpk[q - qs] = i | ((off + 1) << 16);
            qes[q - qs]   = g_es[base + i];
            qes01[q - qs] = g_es01[base + i];
        }
    }
    __syncthreads();

    {
        int qg = tid >> 6, d = tid & 63;
        float totd = Tot[d], prad = prA[d], prbd = prB[d];
        float tma = totd - prad;
        for (int q = qg; q < nq; q += 4) {
            int pk = qpk[q];
            int i = pk & 0xFFFF;
            int offp = pk >> 16;
            float es = qes[q];
            float val;
            if (offp == 0) {
                val = es * totd;
            } else {
                int off = offp - 1;
                val = es * (tma - locA[off * 64 + d])
                    + qes01[q] * (prbd + locB[off * 64 + d]);
            }
            store_hilo((size_t)(b * NN + i) * CC + hh * DD + d, val);
        }
    }
}

// ---------------------------------------------------------------------------
// k5m: out = h' @ out_W + b via mma.sync bf16 hi/lo, cp.async pipeline.
// Slot = Ah(32x72) Al Bh(64x72) Bl = 27648 B; 4 slots -> 2 CTA/SM.
// ---------------------------------------------------------------------------
#define K5_SLOT 27648
#define K5_SMEM (4 * K5_SLOT)

__global__ __launch_bounds__(256) void k5m(const float* __restrict__ ob,
                                           float* __restrict__ out) {
    extern __shared__ __nv_bfloat16 smb[];
    int tid = threadIdx.x, lane = tid & 31, w = tid >> 5;
    int mi = w & 1, nc = w >> 1;
    int r0 = blockIdx.x * 32;
    int arow = tid >> 3, ag = tid & 7;
    uint32_t sbase = smem_u32(smb);

    const __nv_bfloat16* hpHrow = g_hpH + (size_t)(r0 + arow) * CC + ag * 8;
    const __nv_bfloat16* hpLrow = g_hpL + (size_t)(r0 + arow) * CC + ag * 8;

    GRID_DEP_WAIT();   // kD's g_hpH/L (and kS's g_oWH/L, transitively) visible

#define K5_ISSUE(c) do {                                                      \
        int _c = (c);                                                         \
        uint32_t _sb = sbase + (uint32_t)(_c & 3) * K5_SLOT;                  \
        uint32_t _da = _sb + (uint32_t)(arow * 72 + ag * 8) * 2;              \
        CP16(_da,        hpHrow + _c * 64);                                   \
        CP16(_da + 4608, hpLrow + _c * 64);                                   \
        _Pragma("unroll")                                                     \
        for (int _p = 0; _p < 2; _p++) {                                      \
            int _idx = _p * 256 + tid;                                        \
            int _row = _idx >> 3, _g = _idx & 7;                              \
            uint32_t _db = _sb + 9216 + (uint32_t)(_row * 72 + _g * 8) * 2;   \
            CP16(_db,        &g_oWH[(size_t)(_c * 64 + _row) * 64 + _g * 8]); \
            CP16(_db + 9216, &g_oWL[(size_t)(_c * 64 + _row) * 64 + _g * 8]); \
        }                                                                     \
        CP_COMMIT();                                                          \
    } while (0)

    K5_ISSUE(0);
    K5_ISSUE(1);
    K5_ISSUE(2);

    uint32_t aoff = (uint32_t)(((((lane >> 3) & 1) * 8 + (lane & 7)) + mi * 16) * 72
                               + (lane >> 4) * 8) * 2;
    uint32_t bB = (uint32_t)((lane & 15) * 72 + (lane >> 4) * 8) * 2
                  + (uint32_t)nc * 32;

    float acc[2][4] = {};

    for (int c = 0; c < 8; c++) {
        CP_WAIT2();
        __syncthreads();
        if (c + 3 < 8) { K5_ISSUE(c + 3); } else { CP_COMMIT(); }

        uint32_t sb = sbase + (uint32_t)(c & 3) * K5_SLOT;
        uint32_t aAh = sb + aoff;
        uint32_t aAl = aAh + 4608;
        uint32_t aBh = sb + 9216 + bB;
        uint32_t aBl = aBh + 9216;
#pragma unroll
        for (int kk = 0; kk < 4; kk++) {
            uint32_t ka = (uint32_t)(kk * 32);
            uint32_t rb = (uint32_t)(kk * 16 * 144);
            uint32_t ah0, ah1, ah2, ah3, al0, al1, al2, al3;
            uint32_t bh0, bh1, bh2, bh3, bl0, bl1, bl2, bl3;
            LDSM4(ah0, ah1, ah2, ah3, aAh + ka);
            LDSM4(al0, al1, al2, al3, aAl + ka);
            LDSM_T4(bh0, bh1, bh2, bh3, aBh + rb);
            LDSM_T4(bl0, bl1, bl2, bl3, aBl + rb);
            MMA16816(acc[0][0], acc[0][1], acc[0][2], acc[0][3],
                     ah0, ah1, ah2, ah3, bh0, bh1);
            MMA16816(acc[1][0], acc[1][1], acc[1][2], acc[1][3],
                     ah0, ah1, ah2, ah3, bh2, bh3);
            MMA16816(acc[0][0], acc[0][1], acc[0][2], acc[0][3],
                     ah0, ah1, ah2, ah3, bl0, bl1);
            MMA16816(acc[1][0], acc[1][1], acc[1][2], acc[1][3],
                     ah0, ah1, ah2, ah3, bl2, bl3);
            MMA16816(acc[0][0], acc[0][1], acc[0][2], acc[0][3],
                     al0, al1, al2, al3, bh0, bh1);
            MMA16816(acc[1][0], acc[1][1], acc[1][2], acc[1][3],
                     al0, al1, al2, al3, bh2, bh3);
        }
    }

    int gr = lane >> 2, c2 = (lane & 3) * 2;
    int row0 = r0 + mi * 16 + gr;
#pragma unroll
    for (int t = 0; t < 2; t++) {
        int col = nc * 16 + t * 8 + c2;
        float b0 = ob[col], b1 = ob[col + 1];
        float2 o0 = {acc[t][0] + b0, acc[t][1] + b1};
        float2 o1 = {acc[t][2] + b0, acc[t][3] + b1};
        *(float2*)&out[(size_t)row0 * DD + col] = o0;
        *(float2*)&out[(size_t)(row0 + 8) * DD + col] = o1;
    }
#undef K5_ISSUE
}

// ---------------------------------------------------------------------------
extern "C" void kernel_launch(void* const* d_in, const int* in_sizes, int n_in,
                              void* d_out, int out_size) {
    const float* h    = (const float*)d_in[0];
    const float* W    = (const float*)d_in[2];
    const float* a    = (const float*)d_in[3];
    const float* oW   = (const float*)d_in[4];
    const float* ob   = (const float*)d_in[5];
    float* out = (float*)d_out;

    cudaFuncSetAttribute(kS_all, cudaFuncAttributeMaxDynamicSharedMemorySize,
                         KS_SMEM);
    cudaFuncSetAttribute(kD_apply, cudaFuncAttributeMaxDynamicSharedMemorySize,
                         KD_SMEM);
    cudaFuncSetAttribute(k5m, cudaFuncAttributeMaxDynamicSharedMemorySize,
                         K5_SMEM);

    // k1x: plain launch (chain head)
    k1x<<<dim3(HH, (BB*NN)/64), 256>>>(h, W, a);

    // PDL attribute: allow each dependent grid's launch to overlap the
    // predecessor's tail; kernels gate data access with griddepcontrol.wait.
    cudaLaunchAttribute pdl;
    pdl.id = cudaLaunchAttributeProgrammaticStreamSerialization;
    pdl.val.programmaticStreamSerializationAllowed = 1;

    {
        cudaLaunchConfig_t cfg = {};
        cfg.gridDim = dim3(BB*HH, 1, 1);
        cfg.blockDim = dim3(1024, 1, 1);
        cfg.dynamicSmemBytes = KS_SMEM;
        cfg.stream = 0;
        cfg.attrs = &pdl;
        cfg.numAttrs = 1;
        cudaLaunchKernelEx(&cfg, kS_all, oW);
    }
    {
        cudaLaunchConfig_t cfg = {};
        cfg.gridDim = dim3(BB*HH*16, 1, 1);
        cfg.blockDim = dim3(256, 1, 1);
        cfg.dynamicSmemBytes = KD_SMEM;
        cfg.stream = 0;
        cfg.attrs = &pdl;
        cfg.numAttrs = 1;
        cudaLaunchKernelEx(&cfg, kD_apply);
    }
    {
        cudaLaunchConfig_t cfg = {};
        cfg.gridDim = dim3((BB*NN)/32, 1, 1);
        cfg.blockDim = dim3(256, 1, 1);
        cfg.dynamicSmemBytes = K5_SMEM;
        cfg.stream = 0;
        cfg.attrs = &pdl;
        cfg.numAttrs = 1;
        cudaLaunchKernelEx(&cfg, k5m, ob, out);
    }
}

// round 16
// speedup vs baseline: 1.3544x; 1.0821x over previous
#include <cuda_runtime.h>
#include <cuda_bf16.h>
#include <cstdint>
#include <cstddef>

#define BB 8
#define NN 1024
#define HH 8
#define DD 64
#define CC (HH*DD)   // 512

// Scratch
__device__ __nv_bfloat16 g_hpH[BB*NN*CC];
__device__ __nv_bfloat16 g_hpL[BB*NN*CC];
__device__ __nv_bfloat16 g_oWH[CC*DD];
__device__ __nv_bfloat16 g_oWL[CC*DD];
__device__ float g_s   [BB*HH*NN];
__device__ float g_t   [BB*HH*NN];
__device__ float g_es  [BB*HH*NN];
__device__ float g_es01[BB*HH*NN];
__device__ float g_et  [BB*HH*NN];
__device__ float g_et01[BB*HH*NN];
__device__ float g_Wh[BB*NN*CC];
// sort/scan pipeline scratch (16 chunks of 64)
__device__ int   g_tpi [BB*HH*NN];
__device__ float g_wA  [BB*HH*NN];
__device__ float g_wB  [BB*HH*NN];
__device__ int   g_ci  [BB*HH*NN];
__device__ int   g_qord[BB*HH*NN];
__device__ int   g_bofG[BB*HH*32];
__device__ float g_prA [BB*HH*16*64];
__device__ float g_prB [BB*HH*16*64];
__device__ float g_TotA[BB*HH*64];

__device__ __forceinline__ uint32_t smem_u32(const void* p) {
    uint32_t a;
    asm("{ .reg .u64 t; cvta.to.shared.u64 t, %1; cvt.u32.u64 %0, t; }" : "=r"(a) : "l"(p));
    return a;
}
#define GRID_DEP_WAIT() asm volatile("griddepcontrol.wait;" ::: "memory")

#define LDSM4(r0, r1, r2, r3, addr) \
    asm volatile("ldmatrix.sync.aligned.m8n8.x4.shared.b16 {%0,%1,%2,%3}, [%4];" \
                 : "=r"(r0), "=r"(r1), "=r"(r2), "=r"(r3) : "r"(addr))
#define LDSM_T4(r0, r1, r2, r3, addr) \
    asm volatile("ldmatrix.sync.aligned.m8n8.x4.trans.shared.b16 {%0,%1,%2,%3}, [%4];" \
                 : "=r"(r0), "=r"(r1), "=r"(r2), "=r"(r3) : "r"(addr))
#define MMA16816(d0,d1,d2,d3, a0,a1,a2,a3, b0,b1) \
    asm volatile("mma.sync.aligned.m16n8k16.row.col.f32.bf16.bf16.f32 " \
                 "{%0,%1,%2,%3}, {%4,%5,%6,%7}, {%8,%9}, {%0,%1,%2,%3};" \
                 : "+f"(d0), "+f"(d1), "+f"(d2), "+f"(d3) \
                 : "r"(a0), "r"(a1), "r"(a2), "r"(a3), "r"(b0), "r"(b1))
#define CP16(dst, src) \
    asm volatile("cp.async.cg.shared.global [%0], [%1], 16;" :: "r"(dst), "l"(src))
#define CP_COMMIT() asm volatile("cp.async.commit_group;" ::: "memory")
#define CP_WAIT2()  asm volatile("cp.async.wait_group 2;" ::: "memory")

__device__ __forceinline__ uint32_t pack_bf16(float a, float b) {
    __nv_bfloat162 t = __floats2bfloat162_rn(a, b);
    return *(uint32_t*)&t;
}
__device__ __forceinline__ uint32_t split_pair(float e0, float e1, uint32_t& lo) {
    float h0 = __bfloat162float(__float2bfloat16_rn(e0));
    float h1 = __bfloat162float(__float2bfloat16_rn(e1));
    lo = pack_bf16(e0 - h0, e1 - h1);
    return pack_bf16(h0, h1);
}
__device__ __forceinline__ void split4(float4 v, uint2& hi, uint2& lo) {
    uint32_t l0, l1;
    uint32_t h0 = split_pair(v.x, v.y, l0);
    uint32_t h1 = split_pair(v.z, v.w, l1);
    hi.x = h0; hi.y = h1;
    lo.x = l0; lo.y = l1;
}

// ---------------------------------------------------------------------------
// k1x: Wh = h @ W (64 rows x one head per block) via mma.sync bf16 hi/lo,
//      fused with s/t/exp. Epilogue stages acc through smem (aliases A tiles)
//      so the s/t dots and the g_Wh store read identical values.
// grid (8 heads, 128 row-tiles), 256 threads, 36.9 KB dynamic smem.
// ---------------------------------------------------------------------------
#define X_AH 0          /* bf16 element offsets; each tile 64x72 = 4608 */
#define X_AL 4608
#define X_BH 9216
#define X_BL 13824
#define X_ELEMS 18432
#define X_SMEM (X_ELEMS * 2)

__global__ __launch_bounds__(256) void k1x(const float* __restrict__ h,
                                           const float* __restrict__ W,
                                           const float* __restrict__ a) {
    extern __shared__ __nv_bfloat16 smx[];
    __shared__ float as[128];
    int tid = threadIdx.x, lane = tid & 31, w = tid >> 5;
    int mi = w & 3, nj = w >> 2;     // m16 tile, n32 half
    int hh = blockIdx.x;
    int r0 = blockIdx.y * 64;
    int c0 = hh * 64;
    if (tid < 128) as[tid] = a[tid];

    // fill A (h rows x k) and B (k rows x n cols) hi/lo, 4 float4 each
#pragma unroll
    for (int p = 0; p < 4; p++) {
        int idx = p * 256 + tid;
        int r = idx >> 4, k4 = idx & 15;
        float4 hv = *(const float4*)&h[(size_t)(r0 + r) * 64 + k4 * 4];
        uint2 hi, lo;
        split4(hv, hi, lo);
        *(uint2*)&smx[X_AH + r * 72 + k4 * 4] = hi;
        *(uint2*)&smx[X_AL + r * 72 + k4 * 4] = lo;
        float4 wv = *(const float4*)&W[(size_t)r * CC + c0 + k4 * 4];
        split4(wv, hi, lo);
        *(uint2*)&smx[X_BH + r * 72 + k4 * 4] = hi;
        *(uint2*)&smx[X_BL + r * 72 + k4 * 4] = lo;
    }
    __syncthreads();

    uint32_t sb = smem_u32(smx);
    uint32_t aoff = (uint32_t)(((((lane >> 3) & 1) * 8 + (lane & 7)) + mi * 16) * 72
                               + (lane >> 4) * 8) * 2;
    uint32_t boff = (uint32_t)((lane & 15) * 72 + (lane >> 4) * 8) * 2
                    + (uint32_t)nj * 64;
    uint32_t aAh = sb + X_AH * 2 + aoff;
    uint32_t aAl = sb + X_AL * 2 + aoff;
    uint32_t aBh = sb + X_BH * 2 + boff;
    uint32_t aBl = sb + X_BL * 2 + boff;

    float acc[4][4] = {};
#pragma unroll
    for (int kk = 0; kk < 4; kk++) {
        uint32_t ka = (uint32_t)(kk * 32);
        uint32_t rb = (uint32_t)(kk * 16 * 144);
        uint32_t ah0, ah1, ah2, ah3, al0, al1, al2, al3;
        LDSM4(ah0, ah1, ah2, ah3, aAh + ka);
        LDSM4(al0, al1, al2, al3, aAl + ka);
#pragma unroll
        for (int u = 0; u < 2; u++) {
            uint32_t nb = rb + (uint32_t)u * 32;
            uint32_t bh0, bh1, bh2, bh3, bl0, bl1, bl2, bl3;
            LDSM_T4(bh0, bh1, bh2, bh3, aBh + nb);
            LDSM_T4(bl0, bl1, bl2, bl3, aBl + nb);
            MMA16816(acc[2*u][0], acc[2*u][1], acc[2*u][2], acc[2*u][3],
                     ah0, ah1, ah2, ah3, bh0, bh1);
            MMA16816(acc[2*u+1][0], acc[2*u+1][1], acc[2*u+1][2], acc[2*u+1][3],
                     ah0, ah1, ah2, ah3, bh2, bh3);
            MMA16816(acc[2*u][0], acc[2*u][1], acc[2*u][2], acc[2*u][3],
                     ah0, ah1, ah2, ah3, bl0, bl1);
            MMA16816(acc[2*u+1][0], acc[2*u+1][1], acc[2*u+1][2], acc[2*u+1][3],
                     ah0, ah1, ah2, ah3, bl2, bl3);
            MMA16816(acc[2*u][0], acc[2*u][1], acc[2*u][2], acc[2*u][3],
                     al0, al1, al2, al3, bh0, bh1);
            MMA16816(acc[2*u+1][0], acc[2*u+1][1], acc[2*u+1][2], acc[2*u+1][3],
                     al0, al1, al2, al3, bh2, bh3);
        }
    }

    __syncthreads();   // all ldsm reads done -> safe to alias A region
    float* Cs = (float*)smx;   // 64 x 68 fp32 (17408 B <= 18432 B of Ah+Al)
    {
        int gr = lane >> 2, c2 = (lane & 3) * 2;
        int rA = mi * 16 + gr;
#pragma unroll
        for (int t = 0; t < 4; t++) {
            int col = nj * 32 + t * 8 + c2;
            float2 o0 = {acc[t][0], acc[t][1]};
            float2 o1 = {acc[t][2], acc[t][3]};
            *(float2*)&Cs[rA * 68 + col] = o0;
            *(float2*)&Cs[(rA + 8) * 68 + col] = o1;
        }
    }
    __syncthreads();

    if (tid < 64) {
        int row = tid;
        float s = 0.f, t = 0.f;
#pragma unroll 8
        for (int k = 0; k < 64; k++) {
            float val = Cs[row * 68 + k];
            s = fmaf(val, as[k], s);
            t = fmaf(val, as[64 + k], t);
        }
        int gr = r0 + row;
        int b = gr >> 10, n = gr & (NN - 1);
        int o = (b * HH + hh) * NN + n;
        g_s[o] = s;                 g_t[o] = t;
        g_es[o]   = __expf(s);      g_es01[o] = __expf(0.01f * s);
        g_et[o]   = __expf(t);      g_et01[o] = __expf(0.01f * t);
    }
#pragma unroll
    for (int p = 0; p < 4; p++) {
        int idx = p * 256 + tid;
        int r = idx >> 4, k4 = idx & 15;
        float4 o = *(const float4*)&Cs[r * 68 + k4 * 4];
        *(float4*)&g_Wh[(size_t)(r0 + r) * CC + c0 + k4 * 4] = o;
    }
}

// ---------------------------------------------------------------------------
__device__ __forceinline__ int ub1024(const float* __restrict__ arr, float key) {
    int lo = 0, hi = 1024;
    while (lo < hi) {
        int mid = (lo + hi) >> 1;
        if (arr[mid] <= key) lo = mid + 1; else hi = mid;
    }
    return lo;
}

__device__ __forceinline__ void shfl_cex(int e, int k, int j,
                                         float& ks, int& is,
                                         float& kt2, int& it2) {
    bool up = ((e & k) == 0);
    bool amLow = ((e & j) == 0);
    float pks = __shfl_xor_sync(0xFFFFFFFFu, ks, j);
    int   pis = __shfl_xor_sync(0xFFFFFFFFu, is, j);
    float pkt = __shfl_xor_sync(0xFFFFFFFFu, kt2, j);
    int   pit = __shfl_xor_sync(0xFFFFFFFFu, it2, j);
    bool c1 = amLow ? ((ks > pks) == up) : ((pks > ks) == up);
    if (c1) { ks = pks; is = pis; }
    bool c2 = amLow ? ((kt2 > pkt) == up) : ((pkt > kt2) == up);
    if (c2) { kt2 = pkt; it2 = pit; }
}

// ---------------------------------------------------------------------------
// kS: one block per (b,h), 1024 threads. Folds out_W hi/lo split (before the
//     PDL wait). Shuffle bitonic sorts, warp scans, Z, 17 buckets, 16 chunk
//     sums, coarse prefixes.
// ---------------------------------------------------------------------------
#define S_SV    0
#define S_TV    1024
#define S_SIDX  2048
#define S_TPI   3072
#define S_SCANA 4096
#define S_SCANB 6144
#define S_WAS   8192
#define S_WBS   9216
#define S_PARTA 10240
#define S_PARTB 11264
#define S_BOFF  12288   /* 32 ints */
#define S_CNT   12320   /* 32 ints */
#define KS_FLOATS 12352
#define KS_SMEM (KS_FLOATS * 4)

__global__ __launch_bounds__(1024) void kS_all(const float* __restrict__ oW) {
    extern __shared__ float sm[];
    float* sv    = sm + S_SV;
    float* tv    = sm + S_TV;
    int*   sidx  = (int*)(sm + S_SIDX);
    int*   tpi   = (int*)(sm + S_TPI);
    float* scanA = sm + S_SCANA;
    float* scanB = sm + S_SCANB;
    float* wAs   = sm + S_WAS;
    float* wBs   = sm + S_WBS;
    float* partA = sm + S_PARTA;
    float* partB = sm + S_PARTB;
    int*   boff  = (int*)(sm + S_BOFF);
    int*   cnt   = (int*)(sm + S_CNT);

    int tid = threadIdx.x;
    int lane = tid & 31, wrp = tid >> 5;
    int bh = blockIdx.x;
    int b = bh >> 3, hh = bh & 7;
    int base = bh * NN;

    {
        int i = bh * 1024 + tid;
        if (i < CC * DD) {
            float v = oW[i];
            __nv_bfloat16 hi = __float2bfloat16_rn(v);
            g_oWH[i] = hi;
            g_oWL[i] = __float2bfloat16_rn(v - __bfloat162float(hi));
        }
    }
    if (tid < 32) { boff[tid] = 0; cnt[tid] = 0; }

    GRID_DEP_WAIT();

    float s0 = g_s[base + tid];
    sv[tid] = s0;  sidx[tid] = tid;
    tv[tid] = g_t[base + tid];  tpi[tid] = tid;
    __syncthreads();

    {
        float ksv = sv[tid]; int kis = sidx[tid];
        float ktv = tv[tid]; int kit = tpi[tid];
#pragma unroll
        for (int k = 2; k <= 32; k <<= 1)
#pragma unroll
            for (int j = k >> 1; j > 0; j >>= 1)
                shfl_cex(tid, k, j, ksv, kis, ktv, kit);
        sv[tid] = ksv; sidx[tid] = kis; tv[tid] = ktv; tpi[tid] = kit;
        __syncthreads();
        for (int k = 64; k <= 1024; k <<= 1) {
            for (int j = k >> 1; j >= 32; j >>= 1) {
                int ixj = tid ^ j;
                if (ixj > tid) {
                    bool up = ((tid & k) == 0);
                    float av = sv[tid], bq = sv[ixj];
                    if ((av > bq) == up) {
                        sv[tid] = bq; sv[ixj] = av;
                        int tmp = sidx[tid]; sidx[tid] = sidx[ixj]; sidx[ixj] = tmp;
                    }
                    float at = tv[tid], bt = tv[ixj];
                    if ((at > bt) == up) {
                        tv[tid] = bt; tv[ixj] = at;
                        int tmp = tpi[tid]; tpi[tid] = tpi[ixj]; tpi[ixj] = tmp;
                    }
                }
                __syncthreads();
            }
            ksv = sv[tid]; kis = sidx[tid]; ktv = tv[tid]; kit = tpi[tid];
#pragma unroll
            for (int j = 16; j > 0; j >>= 1)
                shfl_cex(tid, k, j, ksv, kis, ktv, kit);
            sv[tid] = ksv; sidx[tid] = kis; tv[tid] = ktv; tpi[tid] = kit;
            __syncthreads();
        }
    }

    {
        int io = sidx[tid];
        float aA = g_es[base + io];
        float aB = g_es01[base + io];
#pragma unroll
        for (int d = 1; d < 32; d <<= 1) {
            float uA = __shfl_up_sync(0xFFFFFFFFu, aA, d);
            float uB = __shfl_up_sync(0xFFFFFFFFu, aB, d);
            if (lane >= d) { aA += uA; aB += uB; }
        }
        if (lane == 31) { scanA[1024 + wrp] = aA; scanB[1024 + wrp] = aB; }
        __syncthreads();
        if (wrp == 0) {
            float wa = scanA[1024 + lane], wb = scanB[1024 + lane];
#pragma unroll
            for (int d = 1; d < 32; d <<= 1) {
                float uA = __shfl_up_sync(0xFFFFFFFFu, wa, d);
                float uB = __shfl_up_sync(0xFFFFFFFFu, wb, d);
                if (lane >= d) { wa += uA; wb += uB; }
            }
            scanA[1024 + lane] = wa; scanB[1024 + lane] = wb;
        }
        __syncthreads();
        float offA = wrp ? scanA[1024 + wrp - 1] : 0.f;
        float offB = wrp ? scanB[1024 + wrp - 1] : 0.f;
        scanA[tid] = aA + offA;
        scanB[tid] = aB + offB;
    }
    __syncthreads();
    const float* inclA = scanA;
    const float* inclB = scanB;
    float ES_tot = inclA[1023];

    {
        int cpr = ub1024(sv, -tv[tid]);
        int jo = tpi[tid];
        float et = g_et[base + jo], et01 = g_et01[base + jo];
        float pa = cpr ? inclA[cpr - 1] : 0.f;
        float pb = cpr ? inclB[cpr - 1] : 0.f;
        float rz = 1.f / (et * (ES_tot - pa) + et01 * pb);
        float wa = et * rz, wb = et01 * rz;
        wAs[tid] = wa;  wBs[tid] = wb;
        g_wA[base + tid] = wa;
        g_wB[base + tid] = wb;
        g_tpi[base + tid] = jo;
    }

    {
        int c = ub1024(tv, -s0);
        g_ci[base + tid] = c;
        int bu = (c == 0) ? 0 : (1 + ((c - 1) >> 6));
        atomicAdd(&boff[bu + 1], 1);
    }
    __syncthreads();

    {
        int ch = tid >> 6;
        int d = tid & 63;
        int m0 = ch * 64;
        float pa = 0.f, pb = 0.f;
#pragma unroll 4
        for (int q = 0; q < 64; q++) {
            int m = m0 + q;
            float v = g_Wh[(size_t)(b * NN + tpi[m]) * CC + hh * DD + d];
            pa = fmaf(wAs[m], v, pa);
            pb = fmaf(wBs[m], v, pb);
        }
        partA[ch * 64 + d] = pa;
        partB[ch * 64 + d] = pb;
    }
    __syncthreads();

    if (tid == 0)
        for (int q = 1; q <= 17; q++) boff[q] += boff[q - 1];
    __syncthreads();

    {
        int c = g_ci[base + tid];
        int bu = (c == 0) ? 0 : (1 + ((c - 1) >> 6));
        int pos = boff[bu] + atomicAdd(&cnt[bu], 1);
        g_qord[base + pos] = tid;
    }
    if (tid < 32) g_bofG[bh * 32 + tid] = boff[tid];

    if (tid < 64) {
        int d = tid;
        float pa = 0.f, pb = 0.f;
#pragma unroll
        for (int ch = 0; ch < 16; ch++) {
            int o = (bh * 16 + ch) * 64 + d;
            g_prA[o] = pa;  g_prB[o] = pb;
            pa += partA[ch * 64 + d];
            pb += partB[ch * 64 + d];
        }
        g_TotA[bh * 64 + d] = pa;
    }
}

// ---------------------------------------------------------------------------
// kD: 64-wide chunks. grid 1024 = bh*16+ch, 256 threads, ~63 KB smem
//     -> 3 CTA/SM.
// ---------------------------------------------------------------------------
#define D_STAGE  0        /* 64 x 64 */
#define D_LOCA   4096
#define D_LOCB   8192
#define D_WA     12288
#define D_WB     12352
#define D_TOT    12416
#define D_PRA    12480
#define D_PRB    12544
#define D_TPI    12608    /* 64 ints */
#define D_QPK    12672    /* 1024 ints */
#define D_QES    13696
#define D_QES01  14720
#define KD_FLOATS 15744
#define KD_SMEM (KD_FLOATS * 4)

__device__ __forceinline__ void store_hilo(size_t o, float val) {
    __nv_bfloat16 hi = __float2bfloat16_rn(val);
    g_hpH[o] = hi;
    g_hpL[o] = __float2bfloat16_rn(val - __bfloat162float(hi));
}

__global__ __launch_bounds__(256) void kD_apply() {
    extern __shared__ float sm[];
    float* stage = sm + D_STAGE;
    float* locA = sm + D_LOCA;
    float* locB = sm + D_LOCB;
    float* wAs  = sm + D_WA;
    float* wBs  = sm + D_WB;
    float* Tot  = sm + D_TOT;
    float* prA  = sm + D_PRA;
    float* prB  = sm + D_PRB;
    int*   tpis = (int*)(sm + D_TPI);
    int*   qpk  = (int*)(sm + D_QPK);
    float* qes  = sm + D_QES;
    float* qes01= sm + D_QES01;

    int tid = threadIdx.x;
    int bh = blockIdx.x >> 4, ch = blockIdx.x & 15;
    int b = bh >> 3, hh = bh & 7;
    int base = bh * NN;
    int cbase = base + ch * 64;

    GRID_DEP_WAIT();

    int qs = (ch == 0) ? g_bofG[bh * 32 + 0] : g_bofG[bh * 32 + ch + 1];
    int qe = g_bofG[bh * 32 + ch + 2];
    int nq = qe - qs;

    if (tid < 64) {
        wAs[tid] = g_wA[cbase + tid];
        wBs[tid] = g_wB[cbase + tid];
        tpis[tid] = g_tpi[cbase + tid];
    } else if (tid < 128) {
        Tot[tid - 64] = g_TotA[bh * 64 + (tid - 64)];
    } else if (tid < 192) {
        prA[tid - 128] = g_prA[(bh * 16 + ch) * 64 + (tid - 128)];
    } else {
        prB[tid - 192] = g_prB[(bh * 16 + ch) * 64 + (tid - 192)];
    }
    __syncthreads();

#pragma unroll
    for (int p = 0; p < 4; p++) {
        int idx = p * 256 + tid;
        int m = idx >> 4, f4 = idx & 15;
        *(float4*)&stage[m * 64 + f4 * 4] =
            *(const float4*)&g_Wh[(size_t)(b * NN + tpis[m]) * CC + hh * DD + f4 * 4];
    }
    __syncthreads();

    if (tid < 128) {
        int half = tid >> 6, d = tid & 63;
        const float* w = half ? wBs : wAs;
        float* loc = half ? locB : locA;
        float run = 0.f;
#pragma unroll 8
        for (int m = 0; m < 64; m++) {
            run = fmaf(w[m], stage[m * 64 + d], run);
            loc[m * 64 + d] = run;
        }
    } else {
        int t2 = tid - 128;
        for (int q = qs + t2; q < qe; q += 128) {
            int i = g_qord[base + q];
            int c = g_ci[base + i];
            int off = c - ch * 64 - 1;
            qpk[q - qs] = i | ((off + 1) << 16);
            qes[q - qs]   = g_es[base + i];
            qes01[q - qs] = g_es01[base + i];
        }
    }
    __syncthreads();

    {
        int qg = tid >> 6, d = tid & 63;
        float totd = Tot[d], prad = prA[d], prbd = prB[d];
        float tma = totd - prad;
        for (int q = qg; q < nq; q += 4) {
            int pk = qpk[q];
            int i = pk & 0xFFFF;
            int offp = pk >> 16;
            float es = qes[q];
            float val;
            if (offp == 0) {
                val = es * totd;
            } else {
                int off = offp - 1;
                val = es * (tma - locA[off * 64 + d])
                    + qes01[q] * (prbd + locB[off * 64 + d]);
            }
            store_hilo((size_t)(b * NN + i) * CC + hh * DD + d, val);
        }
    }
}

// ---------------------------------------------------------------------------
// k5m: out = h' @ out_W + b via mma.sync bf16 hi/lo, cp.async pipeline.
// ---------------------------------------------------------------------------
#define K5_SLOT 27648
#define K5_SMEM (4 * K5_SLOT)

__global__ __launch_bounds__(256) void k5m(const float* __restrict__ ob,
                                           float* __restrict__ out) {
    extern __shared__ __nv_bfloat16 smb[];
    int tid = threadIdx.x, lane = tid & 31, w = tid >> 5;
    int mi = w & 1, nc = w >> 1;
    int r0 = blockIdx.x * 32;
    int arow = tid >> 3, ag = tid & 7;
    uint32_t sbase = smem_u32(smb);

    const __nv_bfloat16* hpHrow = g_hpH + (size_t)(r0 + arow) * CC + ag * 8;
    const __nv_bfloat16* hpLrow = g_hpL + (size_t)(r0 + arow) * CC + ag * 8;

    GRID_DEP_WAIT();

#define K5_ISSUE(c) do {                                                      \
        int _c = (c);                                                         \
        uint32_t _sb = sbase + (uint32_t)(_c & 3) * K5_SLOT;                  \
        uint32_t _da = _sb + (uint32_t)(arow * 72 + ag * 8) * 2;              \
        CP16(_da,        hpHrow + _c * 64);                                   \
        CP16(_da + 4608, hpLrow + _c * 64);                                   \
        _Pragma("unroll")                                                     \
        for (int _p = 0; _p < 2; _p++) {                                      \
            int _idx = _p * 256 + tid;                                        \
            int _row = _idx >> 3, _g = _idx & 7;                              \
            uint32_t _db = _sb + 9216 + (uint32_t)(_row * 72 + _g * 8) * 2;   \
            CP16(_db,        &g_oWH[(size_t)(_c * 64 + _row) * 64 + _g * 8]); \
            CP16(_db + 9216, &g_oWL[(size_t)(_c * 64 + _row) * 64 + _g * 8]); \
        }                                                                     \
        CP_COMMIT();                                                          \
    } while (0)

    K5_ISSUE(0);
    K5_ISSUE(1);
    K5_ISSUE(2);

    uint32_t aoff = (uint32_t)(((((lane >> 3) & 1) * 8 + (lane & 7)) + mi * 16) * 72
                               + (lane >> 4) * 8) * 2;
    uint32_t bB = (uint32_t)((lane & 15) * 72 + (lane >> 4) * 8) * 2
                  + (uint32_t)nc * 32;

    float acc[2][4] = {};

    for (int c = 0; c < 8; c++) {
        CP_WAIT2();
        __syncthreads();
        if (c + 3 < 8) { K5_ISSUE(c + 3); } else { CP_COMMIT(); }

        uint32_t sb = sbase + (uint32_t)(c & 3) * K5_SLOT;
        uint32_t aAh = sb + aoff;
        uint32_t aAl = aAh + 4608;
        uint32_t aBh = sb + 9216 + bB;
        uint32_t aBl = aBh + 9216;
#pragma unroll
        for (int kk = 0; kk < 4; kk++) {
            uint32_t ka = (uint32_t)(kk * 32);
            uint32_t rb = (uint32_t)(kk * 16 * 144);
            uint32_t ah0, ah1, ah2, ah3, al0, al1, al2, al3;
            uint32_t bh0, bh1, bh2, bh3, bl0, bl1, bl2, bl3;
            LDSM4(ah0, ah1, ah2, ah3, aAh + ka);
            LDSM4(al0, al1, al2, al3, aAl + ka);
            LDSM_T4(bh0, bh1, bh2, bh3, aBh + rb);
            LDSM_T4(bl0, bl1, bl2, bl3, aBl + rb);
            MMA16816(acc[0][0], acc[0][1], acc[0][2], acc[0][3],
                     ah0, ah1, ah2, ah3, bh0, bh1);
            MMA16816(acc[1][0], acc[1][1], acc[1][2], acc[1][3],
                     ah0, ah1, ah2, ah3, bh2, bh3);
            MMA16816(acc[0][0], acc[0][1], acc[0][2], acc[0][3],
                     ah0, ah1, ah2, ah3, bl0, bl1);
            MMA16816(acc[1][0], acc[1][1], acc[1][2], acc[1][3],
                     ah0, ah1, ah2, ah3, bl2, bl3);
            MMA16816(acc[0][0], acc[0][1], acc[0][2], acc[0][3],
                     al0, al1, al2, al3, bh0, bh1);
            MMA16816(acc[1][0], acc[1][1], acc[1][2], acc[1][3],
                     al0, al1, al2, al3, bh2, bh3);
        }
    }

    int gr = lane >> 2, c2 = (lane & 3) * 2;
    int row0 = r0 + mi * 16 + gr;
#pragma unroll
    for (int t = 0; t < 2; t++) {
        int col = nc * 16 + t * 8 + c2;
        float b0 = ob[col], b1 = ob[col + 1];
        float2 o0 = {acc[t][0] + b0, acc[t][1] + b1};
        float2 o1 = {acc[t][2] + b0, acc[t][3] + b1};
        *(float2*)&out[(size_t)row0 * DD + col] = o0;
        *(float2*)&out[(size_t)(row0 + 8) * DD + col] = o1;
    }
#undef K5_ISSUE
}

// ---------------------------------------------------------------------------
extern "C" void kernel_launch(void* const* d_in, const int* in_sizes, int n_in,
                              void* d_out, int out_size) {
    const float* h    = (const float*)d_in[0];
    const float* W    = (const float*)d_in[2];
    const float* a    = (const float*)d_in[3];
    const float* oW   = (const float*)d_in[4];
    const float* ob   = (const float*)d_in[5];
    float* out = (float*)d_out;

    cudaFuncSetAttribute(k1x, cudaFuncAttributeMaxDynamicSharedMemorySize,
                         X_SMEM);
    cudaFuncSetAttribute(kS_all, cudaFuncAttributeMaxDynamicSharedMemorySize,
                         KS_SMEM);
    cudaFuncSetAttribute(kD_apply, cudaFuncAttributeMaxDynamicSharedMemorySize,
                         KD_SMEM);
    cudaFuncSetAttribute(k5m, cudaFuncAttributeMaxDynamicSharedMemorySize,
                         K5_SMEM);

    k1x<<<dim3(HH, (BB*NN)/64), 256, X_SMEM>>>(h, W, a);

    cudaLaunchAttribute pdl;
    pdl.id = cudaLaunchAttributeProgrammaticStreamSerialization;
    pdl.val.programmaticStreamSerializationAllowed = 1;

    {
        cudaLaunchConfig_t cfg = {};
        cfg.gridDim = dim3(BB*HH, 1, 1);
        cfg.blockDim = dim3(1024, 1, 1);
        cfg.dynamicSmemBytes = KS_SMEM;
        cfg.stream = 0;
        cfg.attrs = &pdl;
        cfg.numAttrs = 1;
        cudaLaunchKernelEx(&cfg, kS_all, oW);
    }
    {
        cudaLaunchConfig_t cfg = {};
        cfg.gridDim = dim3(BB*HH*16, 1, 1);
        cfg.blockDim = dim3(256, 1, 1);
        cfg.dynamicSmemBytes = KD_SMEM;
        cfg.stream = 0;
        cfg.attrs = &pdl;
        cfg.numAttrs = 1;
        cudaLaunchKernelEx(&cfg, kD_apply);
    }
    {
        cudaLaunchConfig_t cfg = {};
        cfg.gridDim = dim3((BB*NN)/32, 1, 1);
        cfg.blockDim = dim3(256, 1, 1);
        cfg.dynamicSmemBytes = K5_SMEM;
        cfg.stream = 0;
        cfg.attrs = &pdl;
        cfg.numAttrs = 1;
        cudaLaunchKernelEx(&cfg, k5m, ob, out);
    }
}

// round 17
// speedup vs baseline: 1.3769x; 1.0166x over previous
#include <cuda_runtime.h>
#include <cuda_bf16.h>
#include <cstdint>
#include <cstddef>

#define BB 8
#define NN 1024
#define HH 8
#define DD 64
#define CC (HH*DD)   // 512

// Scratch
__device__ __nv_bfloat16 g_hpH[BB*NN*CC];
__device__ __nv_bfloat16 g_hpL[BB*NN*CC];
__device__ __nv_bfloat16 g_oWH[CC*DD];
__device__ __nv_bfloat16 g_oWL[CC*DD];
__device__ float g_s   [BB*HH*NN];
__device__ float g_t   [BB*HH*NN];
__device__ float g_es  [BB*HH*NN];
__device__ float g_es01[BB*HH*NN];
__device__ float g_et  [BB*HH*NN];
__device__ float g_et01[BB*HH*NN];
__device__ float g_Wh[BB*NN*CC];
// sort/scan pipeline scratch (16 chunks of 64)
__device__ int   g_tpi [BB*HH*NN];
__device__ float g_wA  [BB*HH*NN];
__device__ float g_wB  [BB*HH*NN];
__device__ int   g_ci  [BB*HH*NN];
__device__ int   g_qord[BB*HH*NN];
__device__ int   g_bofG[BB*HH*32];
__device__ float g_prA [BB*HH*16*64];
__device__ float g_prB [BB*HH*16*64];
__device__ float g_TotA[BB*HH*64];

__device__ __forceinline__ uint32_t smem_u32(const void* p) {
    uint32_t a;
    asm("{ .reg .u64 t; cvta.to.shared.u64 t, %1; cvt.u32.u64 %0, t; }" : "=r"(a) : "l"(p));
    return a;
}
#define GRID_DEP_WAIT() asm volatile("griddepcontrol.wait;" ::: "memory")

#define LDSM4(r0, r1, r2, r3, addr) \
    asm volatile("ldmatrix.sync.aligned.m8n8.x4.shared.b16 {%0,%1,%2,%3}, [%4];" \
                 : "=r"(r0), "=r"(r1), "=r"(r2), "=r"(r3) : "r"(addr))
#define LDSM_T4(r0, r1, r2, r3, addr) \
    asm volatile("ldmatrix.sync.aligned.m8n8.x4.trans.shared.b16 {%0,%1,%2,%3}, [%4];" \
                 : "=r"(r0), "=r"(r1), "=r"(r2), "=r"(r3) : "r"(addr))
#define MMA16816(d0,d1,d2,d3, a0,a1,a2,a3, b0,b1) \
    asm volatile("mma.sync.aligned.m16n8k16.row.col.f32.bf16.bf16.f32 " \
                 "{%0,%1,%2,%3}, {%4,%5,%6,%7}, {%8,%9}, {%0,%1,%2,%3};" \
                 : "+f"(d0), "+f"(d1), "+f"(d2), "+f"(d3) \
                 : "r"(a0), "r"(a1), "r"(a2), "r"(a3), "r"(b0), "r"(b1))
#define CP16(dst, src) \
    asm volatile("cp.async.cg.shared.global [%0], [%1], 16;" :: "r"(dst), "l"(src))
#define CP_COMMIT() asm volatile("cp.async.commit_group;" ::: "memory")
#define CP_WAIT2()  asm volatile("cp.async.wait_group 2;" ::: "memory")

__device__ __forceinline__ uint32_t pack_bf16(float a, float b) {
    __nv_bfloat162 t = __floats2bfloat162_rn(a, b);
    return *(uint32_t*)&t;
}
__device__ __forceinline__ uint32_t split_pair(float e0, float e1, uint32_t& lo) {
    float h0 = __bfloat162float(__float2bfloat16_rn(e0));
    float h1 = __bfloat162float(__float2bfloat16_rn(e1));
    lo = pack_bf16(e0 - h0, e1 - h1);
    return pack_bf16(h0, h1);
}
__device__ __forceinline__ void split4(float4 v, uint2& hi, uint2& lo) {
    uint32_t l0, l1;
    uint32_t h0 = split_pair(v.x, v.y, l0);
    uint32_t h1 = split_pair(v.z, v.w, l1);
    hi.x = h0; hi.y = h1;
    lo.x = l0; lo.y = l1;
}

// ---------------------------------------------------------------------------
// k1x: Wh = h @ W (64 rows x one head per block) via mma.sync bf16 hi/lo,
//      fused with s/t/exp.
// ---------------------------------------------------------------------------
#define X_AH 0
#define X_AL 4608
#define X_BH 9216
#define X_BL 13824
#define X_ELEMS 18432
#define X_SMEM (X_ELEMS * 2)

__global__ __launch_bounds__(256) void k1x(const float* __restrict__ h,
                                           const float* __restrict__ W,
                                           const float* __restrict__ a) {
    extern __shared__ __nv_bfloat16 smx[];
    __shared__ float as[128];
    int tid = threadIdx.x, lane = tid & 31, w = tid >> 5;
    int mi = w & 3, nj = w >> 2;
    int hh = blockIdx.x;
    int r0 = blockIdx.y * 64;
    int c0 = hh * 64;
    if (tid < 128) as[tid] = a[tid];

#pragma unroll
    for (int p = 0; p < 4; p++) {
        int idx = p * 256 + tid;
        int r = idx >> 4, k4 = idx & 15;
        float4 hv = *(const float4*)&h[(size_t)(r0 + r) * 64 + k4 * 4];
        uint2 hi, lo;
        split4(hv, hi, lo);
        *(uint2*)&smx[X_AH + r * 72 + k4 * 4] = hi;
        *(uint2*)&smx[X_AL + r * 72 + k4 * 4] = lo;
        float4 wv = *(const float4*)&W[(size_t)r * CC + c0 + k4 * 4];
        split4(wv, hi, lo);
        *(uint2*)&smx[X_BH + r * 72 + k4 * 4] = hi;
        *(uint2*)&smx[X_BL + r * 72 + k4 * 4] = lo;
    }
    __syncthreads();

    uint32_t sb = smem_u32(smx);
    uint32_t aoff = (uint32_t)(((((lane >> 3) & 1) * 8 + (lane & 7)) + mi * 16) * 72
                               + (lane >> 4) * 8) * 2;
    uint32_t boff = (uint32_t)((lane & 15) * 72 + (lane >> 4) * 8) * 2
                    + (uint32_t)nj * 64;
    uint32_t aAh = sb + X_AH * 2 + aoff;
    uint32_t aAl = sb + X_AL * 2 + aoff;
    uint32_t aBh = sb + X_BH * 2 + boff;
    uint32_t aBl = sb + X_BL * 2 + boff;

    float acc[4][4] = {};
#pragma unroll
    for (int kk = 0; kk < 4; kk++) {
        uint32_t ka = (uint32_t)(kk * 32);
        uint32_t rb = (uint32_t)(kk * 16 * 144);
        uint32_t ah0, ah1, ah2, ah3, al0, al1, al2, al3;
        LDSM4(ah0, ah1, ah2, ah3, aAh + ka);
        LDSM4(al0, al1, al2, al3, aAl + ka);
#pragma unroll
        for (int u = 0; u < 2; u++) {
            uint32_t nb = rb + (uint32_t)u * 32;
            uint32_t bh0, bh1, bh2, bh3, bl0, bl1, bl2, bl3;
            LDSM_T4(bh0, bh1, bh2, bh3, aBh + nb);
            LDSM_T4(bl0, bl1, bl2, bl3, aBl + nb);
            MMA16816(acc[2*u][0], acc[2*u][1], acc[2*u][2], acc[2*u][3],
                     ah0, ah1, ah2, ah3, bh0, bh1);
            MMA16816(acc[2*u+1][0], acc[2*u+1][1], acc[2*u+1][2], acc[2*u+1][3],
                     ah0, ah1, ah2, ah3, bh2, bh3);
            MMA16816(acc[2*u][0], acc[2*u][1], acc[2*u][2], acc[2*u][3],
                     ah0, ah1, ah2, ah3, bl0, bl1);
            MMA16816(acc[2*u+1][0], acc[2*u+1][1], acc[2*u+1][2], acc[2*u+1][3],
                     ah0, ah1, ah2, ah3, bl2, bl3);
            MMA16816(acc[2*u][0], acc[2*u][1], acc[2*u][2], acc[2*u][3],
                     al0, al1, al2, al3, bh0, bh1);
            MMA16816(acc[2*u+1][0], acc[2*u+1][1], acc[2*u+1][2], acc[2*u+1][3],
                     al0, al1, al2, al3, bh2, bh3);
        }
    }

    __syncthreads();
    float* Cs = (float*)smx;
    {
        int gr = lane >> 2, c2 = (lane & 3) * 2;
        int rA = mi * 16 + gr;
#pragma unroll
        for (int t = 0; t < 4; t++) {
            int col = nj * 32 + t * 8 + c2;
            float2 o0 = {acc[t][0], acc[t][1]};
            float2 o1 = {acc[t][2], acc[t][3]};
            *(float2*)&Cs[rA * 68 + col] = o0;
            *(float2*)&Cs[(rA + 8) * 68 + col] = o1;
        }
    }
    __syncthreads();

    if (tid < 64) {
        int row = tid;
        float s = 0.f, t = 0.f;
#pragma unroll 8
        for (int k = 0; k < 64; k++) {
            float val = Cs[row * 68 + k];
            s = fmaf(val, as[k], s);
            t = fmaf(val, as[64 + k], t);
        }
        int gr = r0 + row;
        int b = gr >> 10, n = gr & (NN - 1);
        int o = (b * HH + hh) * NN + n;
        g_s[o] = s;                 g_t[o] = t;
        g_es[o]   = __expf(s);      g_es01[o] = __expf(0.01f * s);
        g_et[o]   = __expf(t);      g_et01[o] = __expf(0.01f * t);
    }
#pragma unroll
    for (int p = 0; p < 4; p++) {
        int idx = p * 256 + tid;
        int r = idx >> 4, k4 = idx & 15;
        float4 o = *(const float4*)&Cs[r * 68 + k4 * 4];
        *(float4*)&g_Wh[(size_t)(r0 + r) * CC + c0 + k4 * 4] = o;
    }
}

// ---------------------------------------------------------------------------
__device__ __forceinline__ int ub1024(const float* __restrict__ arr, float key) {
    int lo = 0, hi = 1024;
    while (lo < hi) {
        int mid = (lo + hi) >> 1;
        if (arr[mid] <= key) lo = mid + 1; else hi = mid;
    }
    return lo;
}

__device__ __forceinline__ void shfl_cex(int e, int k, int j,
                                         float& ks, int& is,
                                         float& kt2, int& it2) {
    bool up = ((e & k) == 0);
    bool amLow = ((e & j) == 0);
    float pks = __shfl_xor_sync(0xFFFFFFFFu, ks, j);
    int   pis = __shfl_xor_sync(0xFFFFFFFFu, is, j);
    float pkt = __shfl_xor_sync(0xFFFFFFFFu, kt2, j);
    int   pit = __shfl_xor_sync(0xFFFFFFFFu, it2, j);
    bool c1 = amLow ? ((ks > pks) == up) : ((pks > ks) == up);
    if (c1) { ks = pks; is = pis; }
    bool c2 = amLow ? ((kt2 > pkt) == up) : ((pkt > kt2) == up);
    if (c2) { kt2 = pkt; it2 = pit; }
}

// ---------------------------------------------------------------------------
// kS: one block per (b,h), 1024 threads.
// ---------------------------------------------------------------------------
#define S_SV    0
#define S_TV    1024
#define S_SIDX  2048
#define S_TPI   3072
#define S_SCANA 4096
#define S_SCANB 6144
#define S_WAS   8192
#define S_WBS   9216
#define S_PARTA 10240
#define S_PARTB 11264
#define S_BOFF  12288
#define S_CNT   12320
#define KS_FLOATS 12352
#define KS_SMEM (KS_FLOATS * 4)

__global__ __launch_bounds__(1024) void kS_all(const float* __restrict__ oW) {
    extern __shared__ float sm[];
    float* sv    = sm + S_SV;
    float* tv    = sm + S_TV;
    int*   sidx  = (int*)(sm + S_SIDX);
    int*   tpi   = (int*)(sm + S_TPI);
    float* scanA = sm + S_SCANA;
    float* scanB = sm + S_SCANB;
    float* wAs   = sm + S_WAS;
    float* wBs   = sm + S_WBS;
    float* partA = sm + S_PARTA;
    float* partB = sm + S_PARTB;
    int*   boff  = (int*)(sm + S_BOFF);
    int*   cnt   = (int*)(sm + S_CNT);

    int tid = threadIdx.x;
    int lane = tid & 31, wrp = tid >> 5;
    int bh = blockIdx.x;
    int b = bh >> 3, hh = bh & 7;
    int base = bh * NN;

    {
        int i = bh * 1024 + tid;
        if (i < CC * DD) {
            float v = oW[i];
            __nv_bfloat16 hi = __float2bfloat16_rn(v);
            g_oWH[i] = hi;
            g_oWL[i] = __float2bfloat16_rn(v - __bfloat162float(hi));
        }
    }
    if (tid < 32) { boff[tid] = 0; cnt[tid] = 0; }

    GRID_DEP_WAIT();

    float s0 = g_s[base + tid];
    sv[tid] = s0;  sidx[tid] = tid;
    tv[tid] = g_t[base + tid];  tpi[tid] = tid;
    __syncthreads();

    {
        float ksv = sv[tid]; int kis = sidx[tid];
        float ktv = tv[tid]; int kit = tpi[tid];
#pragma unroll
        for (int k = 2; k <= 32; k <<= 1)
#pragma unroll
            for (int j = k >> 1; j > 0; j >>= 1)
                shfl_cex(tid, k, j, ksv, kis, ktv, kit);
        sv[tid] = ksv; sidx[tid] = kis; tv[tid] = ktv; tpi[tid] = kit;
        __syncthreads();
        for (int k = 64; k <= 1024; k <<= 1) {
            for (int j = k >> 1; j >= 32; j >>= 1) {
                int ixj = tid ^ j;
                if (ixj > tid) {
                    bool up = ((tid & k) == 0);
                    float av = sv[tid], bq = sv[ixj];
                    if ((av > bq) == up) {
                        sv[tid] = bq; sv[ixj] = av;
                        int tmp = sidx[tid]; sidx[tid] = sidx[ixj]; sidx[ixj] = tmp;
                    }
                    float at = tv[tid], bt = tv[ixj];
                    if ((at > bt) == up) {
                        tv[tid] = bt; tv[ixj] = at;
                        int tmp = tpi[tid]; tpi[tid] = tpi[ixj]; tpi[ixj] = tmp;
                    }
                }
                __syncthreads();
            }
            ksv = sv[tid]; kis = sidx[tid]; ktv = tv[tid]; kit = tpi[tid];
#pragma unroll
            for (int j = 16; j > 0; j >>= 1)
                shfl_cex(tid, k, j, ksv, kis, ktv, kit);
            sv[tid] = ksv; sidx[tid] = kis; tv[tid] = ktv; tpi[tid] = kit;
            __syncthreads();
        }
    }

    {
        int io = sidx[tid];
        float aA = g_es[base + io];
        float aB = g_es01[base + io];
#pragma unroll
        for (int d = 1; d < 32; d <<= 1) {
            float uA = __shfl_up_sync(0xFFFFFFFFu, aA, d);
            float uB = __shfl_up_sync(0xFFFFFFFFu, aB, d);
            if (lane >= d) { aA += uA; aB += uB; }
        }
        if (lane == 31) { scanA[1024 + wrp] = aA; scanB[1024 + wrp] = aB; }
        __syncthreads();
        if (wrp == 0) {
            float wa = scanA[1024 + lane], wb = scanB[1024 + lane];
#pragma unroll
            for (int d = 1; d < 32; d <<= 1) {
                float uA = __shfl_up_sync(0xFFFFFFFFu, wa, d);
                float uB = __shfl_up_sync(0xFFFFFFFFu, wb, d);
                if (lane >= d) { wa += uA; wb += uB; }
            }
            scanA[1024 + lane] = wa; scanB[1024 + lane] = wb;
        }
        __syncthreads();
        float offA = wrp ? scanA[1024 + wrp - 1] : 0.f;
        float offB = wrp ? scanB[1024 + wrp - 1] : 0.f;
        scanA[tid] = aA + offA;
        scanB[tid] = aB + offB;
    }
    __syncthreads();
    const float* inclA = scanA;
    const float* inclB = scanB;
    float ES_tot = inclA[1023];

    {
        int cpr = ub1024(sv, -tv[tid]);
        int jo = tpi[tid];
        float et = g_et[base + jo], et01 = g_et01[base + jo];
        float pa = cpr ? inclA[cpr - 1] : 0.f;
        float pb = cpr ? inclB[cpr - 1] : 0.f;
        float rz = 1.f / (et * (ES_tot - pa) + et01 * pb);
        float wa = et * rz, wb = et01 * rz;
        wAs[tid] = wa;  wBs[tid] = wb;
        g_wA[base + tid] = wa;
        g_wB[base + tid] = wb;
        g_tpi[base + tid] = jo;
    }

    {
        int c = ub1024(tv, -s0);
        g_ci[base + tid] = c;
        int bu = (c == 0) ? 0 : (1 + ((c - 1) >> 6));
        atomicAdd(&boff[bu + 1], 1);
    }
    __syncthreads();

    {
        int ch = tid >> 6;
        int d = tid & 63;
        int m0 = ch * 64;
        float pa = 0.f, pb = 0.f;
#pragma unroll 4
        for (int q = 0; q < 64; q++) {
            int m = m0 + q;
            float v = g_Wh[(size_t)(b * NN + tpi[m]) * CC + hh * DD + d];
            pa = fmaf(wAs[m], v, pa);
            pb = fmaf(wBs[m], v, pb);
        }
        partA[ch * 64 + d] = pa;
        partB[ch * 64 + d] = pb;
    }
    __syncthreads();

    if (tid == 0)
        for (int q = 1; q <= 17; q++) boff[q] += boff[q - 1];
    __syncthreads();

    {
        int c = g_ci[base + tid];
        int bu = (c == 0) ? 0 : (1 + ((c - 1) >> 6));
        int pos = boff[bu] + atomicAdd(&cnt[bu], 1);
        g_qord[base + pos] = tid;
    }
    if (tid < 32) g_bofG[bh * 32 + tid] = boff[tid];

    if (tid < 64) {
        int d = tid;
        float pa = 0.f, pb = 0.f;
#pragma unroll
        for (int ch = 0; ch < 16; ch++) {
            int o = (bh * 16 + ch) * 64 + d;
            g_prA[o] = pa;  g_prB[o] = pb;
            pa += partA[ch * 64 + d];
            pb += partB[ch * 64 + d];
        }
        g_TotA[bh * 64 + d] = pa;
    }
}

// ---------------------------------------------------------------------------
// kD: 64-wide chunks. grid 1024 = bh*16+ch, 256 threads, ~63 KB smem.
// ---------------------------------------------------------------------------
#define D_STAGE  0
#define D_LOCA   4096
#define D_LOCB   8192
#define D_WA     12288
#define D_WB     12352
#define D_TOT    12416
#define D_PRA    12480
#define D_PRB    12544
#define D_TPI    12608
#define D_QPK    12672
#define D_QES    13696
#define D_QES01  14720
#define KD_FLOATS 15744
#define KD_SMEM (KD_FLOATS * 4)

__device__ __forceinline__ void store_hilo(size_t o, float val) {
    __nv_bfloat16 hi = __float2bfloat16_rn(val);
    g_hpH[o] = hi;
    g_hpL[o] = __float2bfloat16_rn(val - __bfloat162float(hi));
}

__global__ __launch_bounds__(256) void kD_apply() {
    extern __shared__ float sm[];
    float* stage = sm + D_STAGE;
    float* locA = sm + D_LOCA;
    float* locB = sm + D_LOCB;
    float* wAs  = sm + D_WA;
    float* wBs  = sm + D_WB;
    float* Tot  = sm + D_TOT;
    float* prA  = sm + D_PRA;
    float* prB  = sm + D_PRB;
    int*   tpis = (int*)(sm + D_TPI);
    int*   qpk  = (int*)(sm + D_QPK);
    float* qes  = sm + D_QES;
    float* qes01= sm + D_QES01;

    int tid = threadIdx.x;
    int bh = blockIdx.x >> 4, ch = blockIdx.x & 15;
    int b = bh >> 3, hh = bh & 7;
    int base = bh * NN;
    int cbase = base + ch * 64;

    GRID_DEP_WAIT();

    int qs = (ch == 0) ? g_bofG[bh * 32 + 0] : g_bofG[bh * 32 + ch + 1];
    int qe = g_bofG[bh * 32 + ch + 2];
    int nq = qe - qs;

    if (tid < 64) {
        wAs[tid] = g_wA[cbase + tid];
        wBs[tid] = g_wB[cbase + tid];
        tpis[tid] = g_tpi[cbase + tid];
    } else if (tid < 128) {
        Tot[tid - 64] = g_TotA[bh * 64 + (tid - 64)];
    } else if (tid < 192) {
        prA[tid - 128] = g_prA[(bh * 16 + ch) * 64 + (tid - 128)];
    } else {
        prB[tid - 192] = g_prB[(bh * 16 + ch) * 64 + (tid - 192)];
    }
    __syncthreads();

#pragma unroll
    for (int p = 0; p < 4; p++) {
        int idx = p * 256 + tid;
        int m = idx >> 4, f4 = idx & 15;
        *(float4*)&stage[m * 64 + f4 * 4] =
            *(const float4*)&g_Wh[(size_t)(b * NN + tpis[m]) * CC + hh * DD + f4 * 4];
    }
    __syncthreads();

    if (tid < 128) {
        int half = tid >> 6, d = tid & 63;
        const float* w = half ? wBs : wAs;
        float* loc = half ? locB : locA;
        float run = 0.f;
#pragma unroll 8
        for (int m = 0; m < 64; m++) {
            run = fmaf(w[m], stage[m * 64 + d], run);
            loc[m * 64 + d] = run;
        }
    } else {
        int t2 = tid - 128;
        for (int q = qs + t2; q < qe; q += 128) {
            int i = g_qord[base + q];
            int c = g_ci[base + i];
            int off = c - ch * 64 - 1;
            qpk[q - qs] = i | ((off + 1) << 16);
            qes[q - qs]   = g_es[base + i];
            qes01[q - qs] = g_es01[base + i];
        }
    }
    __syncthreads();

    {
        int qg = tid >> 6, d = tid & 63;
        float totd = Tot[d], prad = prA[d], prbd = prB[d];
        float tma = totd - prad;
        for (int q = qg; q < nq; q += 4) {
            int pk = qpk[q];
            int i = pk & 0xFFFF;
            int offp = pk >> 16;
            float es = qes[q];
            float val;
            if (offp == 0) {
                val = es * totd;
            } else {
                int off = offp - 1;
                val = es * (tma - locA[off * 64 + d])
                    + qes01[q] * (prbd + locB[off * 64 + d]);
            }
            store_hilo((size_t)(b * NN + i) * CC + hh * DD + d, val);
        }
    }
}

// ---------------------------------------------------------------------------
// k5m: out = h' @ out_W + b via mma.sync bf16 hi/lo, cp.async pipeline.
// M=64 rows/block (grid 128) halves B traffic; 8 warps = 4 mi x 2 nc, each
// warp m16 x n32 (4 n8 tiles, 4 independent acc chains). 3 slots of
// Ah/Al/Bh/Bl(64x72 each) = 110.6 KB -> 2 CTA/SM. Issue of chunk c+3 happens
// after the compute barrier (slot reuse); depth ~2 chunk-computes.
// ---------------------------------------------------------------------------
#define K5_AH 0
#define K5_AL 4608
#define K5_BH 9216
#define K5_BL 13824
#define K5_SLOT_E 18432
#define K5_SLOT_B (K5_SLOT_E * 2)
#define K5_SMEM (3 * K5_SLOT_B)

__global__ __launch_bounds__(256) void k5m(const float* __restrict__ ob,
                                           float* __restrict__ out) {
    extern __shared__ __nv_bfloat16 smb[];
    int tid = threadIdx.x, lane = tid & 31, w = tid >> 5;
    int mi = w & 3, nc = w >> 2;
    int r0 = blockIdx.x * 64;
    uint32_t sbase = smem_u32(smb);

    GRID_DEP_WAIT();

#define K5_ISSUE(c) do {                                                      \
        int _c = (c);                                                         \
        uint32_t _sb = sbase + (uint32_t)(_c % 3) * K5_SLOT_B;                \
        _Pragma("unroll")                                                     \
        for (int _p = 0; _p < 2; _p++) {                                      \
            int _idx = _p * 256 + tid;                                        \
            int _row = _idx >> 3, _g = _idx & 7;                              \
            uint32_t _o = (uint32_t)(_row * 72 + _g * 8) * 2;                 \
            const __nv_bfloat16* _ah =                                        \
                &g_hpH[(size_t)(r0 + _row) * CC + _c * 64 + _g * 8];          \
            const __nv_bfloat16* _al =                                        \
                &g_hpL[(size_t)(r0 + _row) * CC + _c * 64 + _g * 8];          \
            CP16(_sb + K5_AH * 2 + _o, _ah);                                  \
            CP16(_sb + K5_AL * 2 + _o, _al);                                  \
            const __nv_bfloat16* _bh =                                        \
                &g_oWH[(size_t)(_c * 64 + _row) * 64 + _g * 8];               \
            const __nv_bfloat16* _bl =                                        \
                &g_oWL[(size_t)(_c * 64 + _row) * 64 + _g * 8];               \
            CP16(_sb + K5_BH * 2 + _o, _bh);                                  \
            CP16(_sb + K5_BL * 2 + _o, _bl);                                  \
        }                                                                     \
        CP_COMMIT();                                                          \
    } while (0)

    K5_ISSUE(0);
    K5_ISSUE(1);
    K5_ISSUE(2);

    uint32_t aoff = (uint32_t)(((((lane >> 3) & 1) * 8 + (lane & 7)) + mi * 16) * 72
                               + (lane >> 4) * 8) * 2;
    uint32_t boff = (uint32_t)((lane & 15) * 72 + (lane >> 4) * 8) * 2
                    + (uint32_t)nc * 64;

    float acc[4][4] = {};

    for (int c = 0; c < 8; c++) {
        CP_WAIT2();
        __syncthreads();           // slot c%3 data visible to all warps

        uint32_t sb = sbase + (uint32_t)(c % 3) * K5_SLOT_B;
        uint32_t aAh = sb + K5_AH * 2 + aoff;
        uint32_t aAl = sb + K5_AL * 2 + aoff;
        uint32_t aBh = sb + K5_BH * 2 + boff;
        uint32_t aBl = sb + K5_BL * 2 + boff;
#pragma unroll
        for (int kk = 0; kk < 4; kk++) {
            uint32_t ka = (uint32_t)(kk * 32);
            uint32_t rb = (uint32_t)(kk * 16 * 144);
            uint32_t ah0, ah1, ah2, ah3, al0, al1, al2, al3;
            LDSM4(ah0, ah1, ah2, ah3, aAh + ka);
            LDSM4(al0, al1, al2, al3, aAl + ka);
#pragma unroll
            for (int u = 0; u < 2; u++) {
                uint32_t nb = rb + (uint32_t)u * 32;
                uint32_t bh0, bh1, bh2, bh3, bl0, bl1, bl2, bl3;
                LDSM_T4(bh0, bh1, bh2, bh3, aBh + nb);
                LDSM_T4(bl0, bl1, bl2, bl3, aBl + nb);
                MMA16816(acc[2*u][0], acc[2*u][1], acc[2*u][2], acc[2*u][3],
                         ah0, ah1, ah2, ah3, bh0, bh1);
                MMA16816(acc[2*u+1][0], acc[2*u+1][1], acc[2*u+1][2], acc[2*u+1][3],
                         ah0, ah1, ah2, ah3, bh2, bh3);
                MMA16816(acc[2*u][0], acc[2*u][1], acc[2*u][2], acc[2*u][3],
                         ah0, ah1, ah2, ah3, bl0, bl1);
                MMA16816(acc[2*u+1][0], acc[2*u+1][1], acc[2*u+1][2], acc[2*u+1][3],
                         ah0, ah1, ah2, ah3, bl2, bl3);
                MMA16816(acc[2*u][0], acc[2*u][1], acc[2*u][2], acc[2*u][3],
                         al0, al1, al2, al3, bh0, bh1);
                MMA16816(acc[2*u+1][0], acc[2*u+1][1], acc[2*u+1][2], acc[2*u+1][3],
                         al0, al1, al2, al3, bh2, bh3);
            }
        }

        __syncthreads();           // all warps done reading slot c%3
        if (c + 3 < 8) { K5_ISSUE(c + 3); } else { CP_COMMIT(); }
    }

    int gr = lane >> 2, c2 = (lane & 3) * 2;
    int row0 = r0 + mi * 16 + gr;
#pragma unroll
    for (int t = 0; t < 4; t++) {
        int col = nc * 32 + t * 8 + c2;
        float b0 = ob[col], b1 = ob[col + 1];
        float2 o0 = {acc[t][0] + b0, acc[t][1] + b1};
        float2 o1 = {acc[t][2] + b0, acc[t][3] + b1};
        *(float2*)&out[(size_t)row0 * DD + col] = o0;
        *(float2*)&out[(size_t)(row0 + 8) * DD + col] = o1;
    }
#undef K5_ISSUE
}

// ---------------------------------------------------------------------------
extern "C" void kernel_launch(void* const* d_in, const int* in_sizes, int n_in,
                              void* d_out, int out_size) {
    const float* h    = (const float*)d_in[0];
    const float* W    = (const float*)d_in[2];
    const float* a    = (const float*)d_in[3];
    const float* oW   = (const float*)d_in[4];
    const float* ob   = (const float*)d_in[5];
    float* out = (float*)d_out;

    cudaFuncSetAttribute(k1x, cudaFuncAttributeMaxDynamicSharedMemorySize,
                         X_SMEM);
    cudaFuncSetAttribute(kS_all, cudaFuncAttributeMaxDynamicSharedMemorySize,
                         KS_SMEM);
    cudaFuncSetAttribute(kD_apply, cudaFuncAttributeMaxDynamicSharedMemorySize,
                         KD_SMEM);
    cudaFuncSetAttribute(k5m, cudaFuncAttributeMaxDynamicSharedMemorySize,
                         K5_SMEM);

    k1x<<<dim3(HH, (BB*NN)/64), 256, X_SMEM>>>(h, W, a);

    cudaLaunchAttribute pdl;
    pdl.id = cudaLaunchAttributeProgrammaticStreamSerialization;
    pdl.val.programmaticStreamSerializationAllowed = 1;

    {
        cudaLaunchConfig_t cfg = {};
        cfg.gridDim = dim3(BB*HH, 1, 1);
        cfg.blockDim = dim3(1024, 1, 1);
        cfg.dynamicSmemBytes = KS_SMEM;
        cfg.stream = 0;
        cfg.attrs = &pdl;
        cfg.numAttrs = 1;
        cudaLaunchKernelEx(&cfg, kS_all, oW);
    }
    {
        cudaLaunchConfig_t cfg = {};
        cfg.gridDim = dim3(BB*HH*16, 1, 1);
        cfg.blockDim = dim3(256, 1, 1);
        cfg.dynamicSmemBytes = KD_SMEM;
        cfg.stream = 0;
        cfg.attrs = &pdl;
        cfg.numAttrs = 1;
        cudaLaunchKernelEx(&cfg, kD_apply);
    }
    {
        cudaLaunchConfig_t cfg = {};
        cfg.gridDim = dim3((BB*NN)/64, 1, 1);
        cfg.blockDim = dim3(256, 1, 1);
        cfg.dynamicSmemBytes = K5_SMEM;
        cfg.stream = 0;
        cfg.attrs = &pdl;
        cfg.numAttrs = 1;
        cudaLaunchKernelEx(&cfg, k5m, ob, out);
    }
}